// round 7
// baseline (speedup 1.0000x reference)
#include <cuda_runtime.h>
#include <cuda_bf16.h>
#include <cstdint>

#define NN   50000
#define DEGQ 16
#define EE   (NN*DEGQ)
#define HH   32
#define FIN  128

// ---------------- scratch (device globals; no allocation) ----------------
__device__ float g_T[(size_t)EE*HH];       // T1 then (in-place) T2  : 102.4MB
__device__ float g_u1[NN*HH];
__device__ float g_v1[NN*HH];
__device__ float g_s2[NN*HH];
__device__ float g_u2[NN*HH];
__device__ float g_v2[NN*HH];

// ---------------- mma.sync helpers ----------------
__device__ __forceinline__ uint32_t smem_u32(const void* p) {
    uint32_t a;
    asm("{ .reg .u64 t; cvta.to.shared.u64 t, %1; cvt.u32.u64 %0, t; }" : "=r"(a) : "l"(p));
    return a;
}
__device__ __forceinline__ void ldsm4(uint32_t* r, uint32_t addr) {
    asm volatile("ldmatrix.sync.aligned.m8n8.x4.shared.b16 {%0,%1,%2,%3}, [%4];"
        : "=r"(r[0]), "=r"(r[1]), "=r"(r[2]), "=r"(r[3]) : "r"(addr));
}
__device__ __forceinline__ void ldsm2(uint32_t* r, uint32_t addr) {
    asm volatile("ldmatrix.sync.aligned.m8n8.x2.shared.b16 {%0,%1}, [%2];"
        : "=r"(r[0]), "=r"(r[1]) : "r"(addr));
}
__device__ __forceinline__ void mma_bf16(float* c, const uint32_t* a, const uint32_t* b) {
    asm volatile("mma.sync.aligned.m16n8k16.row.col.f32.bf16.bf16.f32 "
        "{%0,%1,%2,%3}, {%4,%5,%6,%7}, {%8,%9}, {%0,%1,%2,%3};"
        : "+f"(c[0]), "+f"(c[1]), "+f"(c[2]), "+f"(c[3])
        : "r"(a[0]), "r"(a[1]), "r"(a[2]), "r"(a[3]), "r"(b[0]), "r"(b[1]));
}

// ---- k1 smem layout (dynamic). Row pitch 272B. ----
#define PITCH    272
#define OFF_A1   0
#define OFF_A2   (128*PITCH)            // 34816
#define OFF_W1   (2*128*PITCH)          // 69632  (B = [we1s; wn1p], 64 rows)
#define OFF_W2   (OFF_W1 + 64*PITCH)    // 87040
#define OFF_SX   (OFF_W2 + 64*PITCH)    // 104448 (8 x 34 floats)
#define K1_SMEM  (OFF_SX + 8*34*4)      // 105536
#define SXP 34   // even pitch -> float2 stores stay 8B-aligned

// ============================================================================
// K1: per block 8 nodes / 128 edges.
//   A[e][k] = |X[src][k]-X[dst][k]| -> bf16 split A1+A2 in smem
//   B = [we1s ; wn1p] (64x128) -> bf16 split W1+W2
//   D = A1(W1+W2) + A2W1 via mma.sync: cols 0-31 -> T1 (g_T);
//   cols 32-63 row-summed per node -> s -> Xn1 -> u1/v1/s2.
// Warp mapping (MMA): w&3 = 32-row group, w>>2 = 16-col half.
// ============================================================================
__global__ __launch_bounds__(256, 2) void k1(const float* __restrict__ X,
                                             const int*   __restrict__ dst,
                                             const float* __restrict__ D,
                                             const float* __restrict__ we1s,
                                             const float* __restrict__ wn1p,
                                             const float* __restrict__ bn1p,
                                             const float* __restrict__ bn1s,
                                             const float* __restrict__ we1p,
                                             const float* __restrict__ be1p,
                                             const float* __restrict__ be1s,
                                             const float* __restrict__ wn2s,
                                             const float* __restrict__ bn2p,
                                             const float* __restrict__ bn2s) {
    extern __shared__ unsigned char smb[];
    float* sf = (float*)smb;
    float* sX = (float*)(smb + OFF_SX);
    const uint32_t sb = smem_u32(smb);

    const int tid = threadIdx.x;
    const int blk = blockIdx.x;
    const int w = tid >> 5, l = tid & 31;

    // ---- B convert: [we1s ; wn1p] 64x128 fp32 -> W1,W2 bf16 ----
    #pragma unroll
    for (int r = 0; r < 32; r++) {
        int idx = tid + 256*r;                 // 0..8191
        int n = idx >> 7, k = idx & 127;
        float wv = (n < 32) ? __ldg(we1s + n*128 + k)
                            : __ldg(wn1p + (n-32)*128 + k);
        __nv_bfloat16 w1 = __float2bfloat16(wv);
        __nv_bfloat16 w2 = __float2bfloat16(wv - __bfloat162float(w1));
        uint32_t o = n*PITCH + 2*k;
        *(__nv_bfloat16*)(smb + OFF_W1 + o) = w1;
        *(__nv_bfloat16*)(smb + OFF_W2 + o) = w2;
    }

    // ---- phase B: gather, abs-diff, bf16 split stores ----
    const int node = blk*8 + w;
    const float4 xv = ((const float4*)(X + (size_t)node*FIN))[l];
    const int* de = dst + node*DEGQ;
    #pragma unroll
    for (int j = 0; j < DEGQ; j++) {
        int d = __ldg(de + j);
        float4 g = ((const float4*)(X + (size_t)d*FIN))[l];
        float4 a;
        a.x = fabsf(xv.x - g.x);
        a.y = fabsf(xv.y - g.y);
        a.z = fabsf(xv.z - g.z);
        a.w = fabsf(xv.w - g.w);

        __nv_bfloat16 h0 = __float2bfloat16(a.x);
        __nv_bfloat16 h1 = __float2bfloat16(a.y);
        __nv_bfloat16 h2 = __float2bfloat16(a.z);
        __nv_bfloat16 h3 = __float2bfloat16(a.w);
        __nv_bfloat16 r0 = __float2bfloat16(a.x - __bfloat162float(h0));
        __nv_bfloat16 r1 = __float2bfloat16(a.y - __bfloat162float(h1));
        __nv_bfloat16 r2 = __float2bfloat16(a.z - __bfloat162float(h2));
        __nv_bfloat16 r3 = __float2bfloat16(a.w - __bfloat162float(h3));

        __nv_bfloat162 p01 = __halves2bfloat162(h0, h1);
        __nv_bfloat162 p23 = __halves2bfloat162(h2, h3);
        __nv_bfloat162 q01 = __halves2bfloat162(r0, r1);
        __nv_bfloat162 q23 = __halves2bfloat162(r2, r3);
        uint64_t hiw = (uint64_t)(*(uint32_t*)&p01) | ((uint64_t)(*(uint32_t*)&p23) << 32);
        uint64_t low = (uint64_t)(*(uint32_t*)&q01) | ((uint64_t)(*(uint32_t*)&q23) << 32);

        const int row = w*DEGQ + j;
        uint32_t o = row*PITCH + l*8;
        *(uint64_t*)(smb + OFF_A1 + o) = hiw;
        *(uint64_t*)(smb + OFF_A2 + o) = low;
    }
    __syncthreads();

    // ---- MMA: warp w -> rows 32*(w&3)..+31, col half (w>>2) ----
    {
        const int rg = w & 3, ch = w >> 2;
        float c[2][4][4];
        #pragma unroll
        for (int t = 0; t < 2; t++)
            #pragma unroll
            for (int nt = 0; nt < 4; nt++)
                c[t][nt][0] = c[t][nt][1] = c[t][nt][2] = c[t][nt][3] = 0.f;

        const uint32_t a_base = sb + (uint32_t)((32*rg + (l & 15))*PITCH + (l >> 4)*16);
        const uint32_t b_base = sb + OFF_W1 +
            (uint32_t)((ch*32 + (l & 7))*PITCH + ((l >> 3) & 1)*16);

        #pragma unroll
        for (int ks = 0; ks < 8; ks++) {
            const uint32_t kb = ks*32;
            uint32_t a1[2][4], a2[2][4];
            ldsm4(a1[0], a_base + kb);
            ldsm4(a1[1], a_base + 16*PITCH + kb);
            ldsm4(a2[0], a_base + OFF_A2 + kb);
            ldsm4(a2[1], a_base + OFF_A2 + 16*PITCH + kb);
            #pragma unroll
            for (int nt = 0; nt < 4; nt++) {
                uint32_t b1[2], b2[2];
                const uint32_t bo = b_base + nt*8*PITCH + kb;
                ldsm2(b1, bo);
                ldsm2(b2, bo + (uint32_t)(64*PITCH));
                #pragma unroll
                for (int t = 0; t < 2; t++) {
                    mma_bf16(c[t][nt], a1[t], b1);
                    mma_bf16(c[t][nt], a1[t], b2);
                    mma_bf16(c[t][nt], a2[t], b1);
                }
            }
        }

        if (ch == 0) {
            // T1 -> g_T
            const int r0 = l >> 2, c0 = (l & 3)*2;
            #pragma unroll
            for (int t = 0; t < 2; t++) {
                const size_t base = (size_t)blk*128 + 32*rg + t*16;
                #pragma unroll
                for (int nt = 0; nt < 4; nt++) {
                    *(float2*)&g_T[(base + r0)*HH + nt*8 + c0]     = make_float2(c[t][nt][0], c[t][nt][1]);
                    *(float2*)&g_T[(base + r0 + 8)*HH + nt*8 + c0] = make_float2(c[t][nt][2], c[t][nt][3]);
                }
            }
        } else {
            // row-sum per m16 tile (= per node) -> s into sX
            #pragma unroll
            for (int t = 0; t < 2; t++) {
                const int nd = 2*rg + t;
                #pragma unroll
                for (int nt = 0; nt < 4; nt++) {
                    float p0 = c[t][nt][0] + c[t][nt][2];
                    float p1 = c[t][nt][1] + c[t][nt][3];
                    p0 += __shfl_xor_sync(0xffffffffu, p0, 4);
                    p1 += __shfl_xor_sync(0xffffffffu, p1, 4);
                    p0 += __shfl_xor_sync(0xffffffffu, p0, 8);
                    p1 += __shfl_xor_sync(0xffffffffu, p1, 8);
                    p0 += __shfl_xor_sync(0xffffffffu, p0, 16);
                    p1 += __shfl_xor_sync(0xffffffffu, p1, 16);
                    if (l < 4)
                        *(float2*)&sX[nd*SXP + nt*8 + 2*l] = make_float2(p0, p1);
                }
            }
        }
    }
    __syncthreads();   // MMA reads done; A region reusable

    // ---- stage weights for u1/v1/s2 (alias A region) ----
    float* sP  = sf;
    float* sQ  = sf + 1056;
    float* sW2 = sf + 2112;
    #pragma unroll
    for (int r = 0; r < 4; r++) {
        int idx = tid + 256*r;
        int hh = idx >> 5, h2 = idx & 31;
        float wa = __ldg(we1p + hh*64 + h2);
        float wb = __ldg(we1p + hh*64 + 32 + h2);
        sP[h2*33 + hh] = 0.5f*(wa + wb);
        sQ[h2*33 + hh] = 0.5f*(wb - wa);
        sW2[h2*33 + hh] = __ldg(wn2s + idx);
    }
    __syncthreads();

    // ---- stage 2: Xn1 + u1/v1/s2 (warp w = node w, lane l = h) ----
    const float invD = 1.0f / __ldg(D + node);
    float x = fmaxf(fmaf(sX[w*SXP + l], invD, __ldg(bn1p+l) + __ldg(bn1s+l)), 0.f);

    float u  = __ldg(be1p+l) + __ldg(be1s+l);
    float vv = 0.f;
    float s2 = __ldg(bn2p+l) + __ldg(bn2s+l);
    #pragma unroll
    for (int h2 = 0; h2 < 32; h2++) {
        float xx = __shfl_sync(0xffffffffu, x, h2);
        u  = fmaf(xx, sP[h2*33 + l], u);
        vv = fmaf(xx, sQ[h2*33 + l], vv);
        s2 = fmaf(xx, sW2[h2*33 + l], s2);
    }
    g_u1[node*HH + l] = u;
    g_v1[node*HH + l] = vv;
    g_s2[node*HH + l] = s2;
}

// ============================================================================
// K2 (HMMA): per block 8 nodes / 128 edges.
//   vals1 = relu(u1[src]+v1[dst]+T1) -> bf16 split A1+A2 (pitch 80)
//   B = [we2s ; wn2p] (64x32) split -> D: cols 0-31 = T2 (g_T in-place),
//   cols 32-63 row-summed -> s -> Xn2 -> u2/v2.
// ============================================================================
#define K2P 80
__global__ __launch_bounds__(256, 2) void k2(const int* __restrict__ dst,
                                             const float* __restrict__ D,
                                             const float* __restrict__ we2s,
                                             const float* __restrict__ wn2p,
                                             const float* __restrict__ we2p,
                                             const float* __restrict__ be2p,
                                             const float* __restrict__ be2s) {
    __shared__ __align__(16) unsigned char sA1[128*K2P];
    __shared__ __align__(16) unsigned char sA2[128*K2P];
    __shared__ __align__(16) unsigned char sB1[64*K2P];
    __shared__ __align__(16) unsigned char sB2[64*K2P];
    __shared__ __align__(16) float sX[8*SXP];
    __shared__ float sP[32*33];
    __shared__ float sQ[32*33];

    const int tid = threadIdx.x, blk = blockIdx.x;
    const int w = tid >> 5, l = tid & 31;

    // ---- B convert: [we2s ; wn2p] 64x32 -> B1,B2 ----
    #pragma unroll
    for (int r = 0; r < 8; r++) {
        int idx = tid + 256*r;                  // 0..2047
        int n = idx >> 5, k = idx & 31;
        float wv = (n < 32) ? __ldg(we2s + n*32 + k) : __ldg(wn2p + (n-32)*32 + k);
        __nv_bfloat16 b1 = __float2bfloat16(wv);
        __nv_bfloat16 b2 = __float2bfloat16(wv - __bfloat162float(b1));
        uint32_t o = n*K2P + 2*k;
        *(__nv_bfloat16*)(sB1 + o) = b1;
        *(__nv_bfloat16*)(sB2 + o) = b2;
    }
    // ---- P/Q for u2/v2 ----
    #pragma unroll
    for (int r = 0; r < 4; r++) {
        int idx = tid + 256*r;
        int hh = idx >> 5, h2 = idx & 31;
        float wa = __ldg(we2p + hh*64 + h2);
        float wb = __ldg(we2p + hh*64 + 32 + h2);
        sP[h2*33 + hh] = 0.5f*(wa + wb);
        sQ[h2*33 + hh] = 0.5f*(wb - wa);
    }

    // ---- phase 1: vals1, split-pack via shfl, store A1/A2 ----
    const int node = blk*8 + w;
    const float u1h = g_u1[node*HH + l];
    const int* de = dst + node*DEGQ;
    const size_t ebase = (size_t)node*DEGQ;
    #pragma unroll
    for (int j = 0; j < DEGQ; j++) {
        int d = __ldg(de + j);
        float val = u1h + g_v1[d*HH + l] + g_T[(ebase + j)*HH + l];
        val = fmaxf(val, 0.f);
        __nv_bfloat16 b1 = __float2bfloat16(val);
        __nv_bfloat16 b2 = __float2bfloat16(val - __bfloat162float(b1));
        uint32_t m1 = (uint32_t)__bfloat16_as_ushort(b1);
        uint32_t m2 = (uint32_t)__bfloat16_as_ushort(b2);
        uint32_t o1 = __shfl_down_sync(0xffffffffu, m1, 1);
        uint32_t o2 = __shfl_down_sync(0xffffffffu, m2, 1);
        if (!(l & 1)) {
            const int row = w*DEGQ + j;
            *(uint32_t*)(sA1 + row*K2P + l*2) = m1 | (o1 << 16);
            *(uint32_t*)(sA2 + row*K2P + l*2) = m2 | (o2 << 16);
        }
    }
    __syncthreads();

    // ---- MMA ----
    {
        const int rg = w & 3, ch = w >> 2;
        float c[2][4][4];
        #pragma unroll
        for (int t = 0; t < 2; t++)
            #pragma unroll
            for (int nt = 0; nt < 4; nt++)
                c[t][nt][0] = c[t][nt][1] = c[t][nt][2] = c[t][nt][3] = 0.f;

        const uint32_t a1_base = smem_u32(sA1) + (uint32_t)((32*rg + (l & 15))*K2P + (l >> 4)*16);
        const uint32_t a2_base = smem_u32(sA2) + (uint32_t)((32*rg + (l & 15))*K2P + (l >> 4)*16);
        const uint32_t b1_base = smem_u32(sB1) + (uint32_t)((ch*32 + (l & 7))*K2P + ((l >> 3) & 1)*16);
        const uint32_t b2_base = smem_u32(sB2) + (uint32_t)((ch*32 + (l & 7))*K2P + ((l >> 3) & 1)*16);

        #pragma unroll
        for (int ks = 0; ks < 2; ks++) {
            const uint32_t kb = ks*32;
            uint32_t a1[2][4], a2[2][4];
            ldsm4(a1[0], a1_base + kb);
            ldsm4(a1[1], a1_base + 16*K2P + kb);
            ldsm4(a2[0], a2_base + kb);
            ldsm4(a2[1], a2_base + 16*K2P + kb);
            #pragma unroll
            for (int nt = 0; nt < 4; nt++) {
                uint32_t b1[2], b2[2];
                ldsm2(b1, b1_base + nt*8*K2P + kb);
                ldsm2(b2, b2_base + nt*8*K2P + kb);
                #pragma unroll
                for (int t = 0; t < 2; t++) {
                    mma_bf16(c[t][nt], a1[t], b1);
                    mma_bf16(c[t][nt], a1[t], b2);
                    mma_bf16(c[t][nt], a2[t], b1);
                }
            }
        }

        if (ch == 0) {
            const int r0 = l >> 2, c0 = (l & 3)*2;
            #pragma unroll
            for (int t = 0; t < 2; t++) {
                const size_t base = (size_t)blk*128 + 32*rg + t*16;
                #pragma unroll
                for (int nt = 0; nt < 4; nt++) {
                    *(float2*)&g_T[(base + r0)*HH + nt*8 + c0]     = make_float2(c[t][nt][0], c[t][nt][1]);
                    *(float2*)&g_T[(base + r0 + 8)*HH + nt*8 + c0] = make_float2(c[t][nt][2], c[t][nt][3]);
                }
            }
        } else {
            #pragma unroll
            for (int t = 0; t < 2; t++) {
                const int nd = 2*rg + t;
                #pragma unroll
                for (int nt = 0; nt < 4; nt++) {
                    float p0 = c[t][nt][0] + c[t][nt][2];
                    float p1 = c[t][nt][1] + c[t][nt][3];
                    p0 += __shfl_xor_sync(0xffffffffu, p0, 4);
                    p1 += __shfl_xor_sync(0xffffffffu, p1, 4);
                    p0 += __shfl_xor_sync(0xffffffffu, p0, 8);
                    p1 += __shfl_xor_sync(0xffffffffu, p1, 8);
                    p0 += __shfl_xor_sync(0xffffffffu, p0, 16);
                    p1 += __shfl_xor_sync(0xffffffffu, p1, 16);
                    if (l < 4)
                        *(float2*)&sX[nd*SXP + nt*8 + 2*l] = make_float2(p0, p1);
                }
            }
        }
    }
    __syncthreads();

    // ---- stage 2: Xn2 + u2/v2 ----
    const float invD = 1.0f / __ldg(D + node);
    float x = fmaxf(fmaf(sX[w*SXP + l], invD, g_s2[node*HH + l]), 0.f);
    float u = __ldg(be2p+l) + __ldg(be2s+l), vv = 0.f;
    #pragma unroll
    for (int h2 = 0; h2 < 32; h2++) {
        float xx = __shfl_sync(0xffffffffu, x, h2);
        u  = fmaf(xx, sP[h2*33 + l], u);
        vv = fmaf(xx, sQ[h2*33 + l], vv);
    }
    g_u2[node*HH + l] = u;
    g_v2[node*HH + l] = vv;
}

// ============================================================================
// K3: out[e] = sigmoid( sum_h relu(u2[src]+v2[dst]+T2[e])*wc[h] + bc )
// smem transpose instead of 160 shfl/thread.
// ============================================================================
__global__ __launch_bounds__(256) void k3(const int* __restrict__ dst,
                                          const float* __restrict__ wc,
                                          const float* __restrict__ bc,
                                          float* __restrict__ out) {
    __shared__ __align__(16) float st[8][32*33];
    const int tid = threadIdx.x, w = tid >> 5, l = tid & 31;
    const size_t e0 = (size_t)blockIdx.x*256 + (size_t)w*32;
    const float wch = __ldg(wc + l);
    #pragma unroll 4
    for (int m = 0; m < 32; m++) {
        const size_t e = e0 + m;
        const int s = (int)(e >> 4);
        const int d = __ldg(dst + e);
        float val = g_u2[s*HH + l] + g_v2[d*HH + l] + g_T[e*HH + l];
        st[w][m*33 + l] = fmaxf(val, 0.f) * wch;
    }
    __syncwarp();
    float res = 0.f;
    #pragma unroll
    for (int k = 0; k < 32; k++)
        res += st[w][l*33 + k];
    const float x = res + __ldg(bc);
    out[e0 + l] = 1.f / (1.f + __expf(-x));
}

// ============================================================================
extern "C" void kernel_launch(void* const* d_in, const int* in_sizes, int n_in,
                              void* d_out, int out_size) {
    const float* X    = (const float*)d_in[0];
    const int*   dst  = (const int*)  d_in[2];
    const float* D    = (const float*)d_in[3];
    const float* wn1p = (const float*)d_in[4];
    const float* bn1p = (const float*)d_in[5];
    const float* bn1s = (const float*)d_in[7];
    const float* we1p = (const float*)d_in[8];
    const float* be1p = (const float*)d_in[9];
    const float* we1s = (const float*)d_in[10];
    const float* be1s = (const float*)d_in[11];
    const float* wn2p = (const float*)d_in[12];
    const float* bn2p = (const float*)d_in[13];
    const float* wn2s = (const float*)d_in[14];
    const float* bn2s = (const float*)d_in[15];
    const float* we2p = (const float*)d_in[16];
    const float* be2p = (const float*)d_in[17];
    const float* we2s = (const float*)d_in[18];
    const float* be2s = (const float*)d_in[19];
    const float* wc   = (const float*)d_in[20];
    const float* bc   = (const float*)d_in[21];
    float* out = (float*)d_out;

    cudaFuncSetAttribute(k1, cudaFuncAttributeMaxDynamicSharedMemorySize, K1_SMEM);

    k1 <<<NN/8, 256, K1_SMEM>>>(X, dst, D, we1s, wn1p, bn1p, bn1s,
                                we1p, be1p, be1s, wn2s, bn2p, bn2s);
    k2 <<<NN/8, 256>>>(dst, D, we2s, wn2p, we2p, be2p, be2s);
    k3 <<<EE/256, 256>>>(dst, wc, bc, out);
}

// round 8
// speedup vs baseline: 1.1650x; 1.1650x over previous
#include <cuda_runtime.h>
#include <cuda_bf16.h>
#include <cstdint>

#define NN   50000
#define DEGQ 16
#define EE   (NN*DEGQ)
#define HH   32
#define FIN  128

// ---------------- scratch (device globals; no allocation) ----------------
__device__ float g_T[(size_t)EE*HH];       // T1 only (never overwritten) : 102.4MB
__device__ float g_u1[NN*HH];
__device__ float g_v1[NN*HH];
__device__ float g_s2[NN*HH];
__device__ float g_u2[NN*HH];
__device__ float g_v2[NN*HH];

// ---------------- mma.sync helpers ----------------
__device__ __forceinline__ uint32_t smem_u32(const void* p) {
    uint32_t a;
    asm("{ .reg .u64 t; cvta.to.shared.u64 t, %1; cvt.u32.u64 %0, t; }" : "=r"(a) : "l"(p));
    return a;
}
__device__ __forceinline__ void ldsm4(uint32_t* r, uint32_t addr) {
    asm volatile("ldmatrix.sync.aligned.m8n8.x4.shared.b16 {%0,%1,%2,%3}, [%4];"
        : "=r"(r[0]), "=r"(r[1]), "=r"(r[2]), "=r"(r[3]) : "r"(addr));
}
__device__ __forceinline__ void ldsm2(uint32_t* r, uint32_t addr) {
    asm volatile("ldmatrix.sync.aligned.m8n8.x2.shared.b16 {%0,%1}, [%2];"
        : "=r"(r[0]), "=r"(r[1]) : "r"(addr));
}
__device__ __forceinline__ void mma_bf16(float* c, const uint32_t* a, const uint32_t* b) {
    asm volatile("mma.sync.aligned.m16n8k16.row.col.f32.bf16.bf16.f32 "
        "{%0,%1,%2,%3}, {%4,%5,%6,%7}, {%8,%9}, {%0,%1,%2,%3};"
        : "+f"(c[0]), "+f"(c[1]), "+f"(c[2]), "+f"(c[3])
        : "r"(a[0]), "r"(a[1]), "r"(a[2]), "r"(a[3]), "r"(b[0]), "r"(b[1]));
}

// ---- k1 smem layout (round-5 proven version). Row pitch 272B. ----
#define PITCH    272
#define OFF_A1   0
#define OFF_A2   (128*PITCH)            // 34816
#define OFF_W1   (2*128*PITCH)          // 69632  (we1s only: 32 rows)
#define OFF_W2   (OFF_W1 + 32*PITCH)    // 78336
#define K1_SMEM  (OFF_W2 + 32*PITCH)    // 87040
// tail region (floats, aliases A1/A2 after MMA epilogue)
#define TL_AS   0
#define TL_WN   (TL_AS + 8*132)
#define TL_P    (TL_WN + 128*33)
#define TL_Q    (TL_P + 32*33)
#define TL_W2   (TL_Q + 32*33)

// ============================================================================
// K1 (round-5 proven): per block 8 nodes / 128 edges.
//   A = |X[src]-X[dst]| -> bf16 split A1+A2; W = we1s -> W1+W2
//   T1 = A1W1 + A1W2 + A2W1 via mma.sync -> g_T
//   asum (fp32) in regs; tail: Xn1 -> u1/v1/s2 via shfl broadcast.
// ============================================================================
__global__ __launch_bounds__(256, 2) void k1(const float* __restrict__ X,
                                             const int*   __restrict__ dst,
                                             const float* __restrict__ D,
                                             const float* __restrict__ we1s,
                                             const float* __restrict__ wn1p,
                                             const float* __restrict__ bn1p,
                                             const float* __restrict__ bn1s,
                                             const float* __restrict__ we1p,
                                             const float* __restrict__ be1p,
                                             const float* __restrict__ be1s,
                                             const float* __restrict__ wn2s,
                                             const float* __restrict__ bn2p,
                                             const float* __restrict__ bn2s) {
    extern __shared__ unsigned char smb[];
    float* sf = (float*)smb;
    const uint32_t sb = smem_u32(smb);

    const int tid = threadIdx.x;
    const int blk = blockIdx.x;
    const int w = tid >> 5, l = tid & 31;

    // ---- W convert: we1s (32 x 128 fp32) -> W1,W2 bf16 ----
    #pragma unroll
    for (int r = 0; r < 16; r++) {
        int idx = tid + 256*r;
        int h = idx >> 7, k = idx & 127;
        float wv = __ldg(we1s + idx);
        __nv_bfloat16 w1 = __float2bfloat16(wv);
        __nv_bfloat16 w2 = __float2bfloat16(wv - __bfloat162float(w1));
        uint32_t o = h*PITCH + 2*k;
        *(__nv_bfloat16*)(smb + OFF_W1 + o) = w1;
        *(__nv_bfloat16*)(smb + OFF_W2 + o) = w2;
    }

    // ---- phase B: gather, abs-diff, fp32 asum, bf16 split stores ----
    const int node = blk*8 + w;
    const float4 xv = ((const float4*)(X + (size_t)node*FIN))[l];
    float4 asum = make_float4(0.f, 0.f, 0.f, 0.f);
    const int* de = dst + node*DEGQ;
    #pragma unroll
    for (int j = 0; j < DEGQ; j++) {
        int d = __ldg(de + j);
        float4 g = ((const float4*)(X + (size_t)d*FIN))[l];
        float4 a;
        a.x = fabsf(xv.x - g.x);
        a.y = fabsf(xv.y - g.y);
        a.z = fabsf(xv.z - g.z);
        a.w = fabsf(xv.w - g.w);
        asum.x += a.x; asum.y += a.y; asum.z += a.z; asum.w += a.w;

        __nv_bfloat16 h0 = __float2bfloat16(a.x);
        __nv_bfloat16 h1 = __float2bfloat16(a.y);
        __nv_bfloat16 h2 = __float2bfloat16(a.z);
        __nv_bfloat16 h3 = __float2bfloat16(a.w);
        __nv_bfloat16 r0 = __float2bfloat16(a.x - __bfloat162float(h0));
        __nv_bfloat16 r1 = __float2bfloat16(a.y - __bfloat162float(h1));
        __nv_bfloat16 r2 = __float2bfloat16(a.z - __bfloat162float(h2));
        __nv_bfloat16 r3 = __float2bfloat16(a.w - __bfloat162float(h3));

        __nv_bfloat162 p01 = __halves2bfloat162(h0, h1);
        __nv_bfloat162 p23 = __halves2bfloat162(h2, h3);
        __nv_bfloat162 q01 = __halves2bfloat162(r0, r1);
        __nv_bfloat162 q23 = __halves2bfloat162(r2, r3);
        uint64_t hiw = (uint64_t)(*(uint32_t*)&p01) | ((uint64_t)(*(uint32_t*)&p23) << 32);
        uint64_t low = (uint64_t)(*(uint32_t*)&q01) | ((uint64_t)(*(uint32_t*)&q23) << 32);

        const int row = w*DEGQ + j;
        uint32_t o = row*PITCH + l*8;
        *(uint64_t*)(smb + OFF_A1 + o) = hiw;
        *(uint64_t*)(smb + OFF_A2 + o) = low;
    }
    __syncthreads();

    // ---- MMA: warp w handles rows wr..wr+15, all 32 output cols ----
    {
        const int wr = w*16;
        float c[4][4];
        #pragma unroll
        for (int nt = 0; nt < 4; nt++)
            c[nt][0] = c[nt][1] = c[nt][2] = c[nt][3] = 0.f;

        const uint32_t a_lane_off = (uint32_t)((wr + (l & 15))*PITCH + (l >> 4)*16);
        const uint32_t b_lane_off = (uint32_t)(((l & 7))*PITCH + ((l >> 3) & 1)*16);

        #pragma unroll
        for (int ks = 0; ks < 8; ks++) {
            uint32_t kb = ks*32;
            uint32_t a1[4], a2[4];
            ldsm4(a1, sb + OFF_A1 + a_lane_off + kb);
            ldsm4(a2, sb + OFF_A2 + a_lane_off + kb);
            #pragma unroll
            for (int nt = 0; nt < 4; nt++) {
                uint32_t b1[2], b2[2];
                uint32_t bo = b_lane_off + (uint32_t)(nt*8*PITCH) + kb;
                ldsm2(b1, sb + OFF_W1 + bo);
                ldsm2(b2, sb + OFF_W2 + bo);
                mma_bf16(c[nt], a1, b1);
                mma_bf16(c[nt], a1, b2);
                mma_bf16(c[nt], a2, b1);
            }
        }

        // epilogue: C frag -> g_T
        const int r0 = l >> 2, c0 = (l & 3)*2;
        const size_t base = (size_t)blk*128 + wr;
        #pragma unroll
        for (int nt = 0; nt < 4; nt++) {
            float* p0 = &g_T[(base + r0)*HH + nt*8 + c0];
            float* p1 = &g_T[(base + r0 + 8)*HH + nt*8 + c0];
            *(float2*)p0 = make_float2(c[nt][0], c[nt][1]);
            *(float2*)p1 = make_float2(c[nt][2], c[nt][3]);
        }
    }
    __syncthreads();   // all smem reads done; reuse for the tail

    // ---- tail: node-level layer-1 + precompute u1/v1/s2 ----
    float* sAs2 = sf + TL_AS;
    float* sWn  = sf + TL_WN;
    float* sP   = sf + TL_P;
    float* sQ   = sf + TL_Q;
    float* sW2  = sf + TL_W2;

    *(float4*)&sAs2[w*132 + 4*l] = asum;
    #pragma unroll
    for (int r = 0; r < 16; r++) {
        int idx = tid + 256*r;
        int hh = idx >> 7, k = idx & 127;
        sWn[k*33 + hh] = __ldg(wn1p + idx);
    }
    #pragma unroll
    for (int r = 0; r < 4; r++) {
        int idx = tid + 256*r;
        int hh = idx >> 5, h2 = idx & 31;
        float wa = __ldg(we1p + hh*64 + h2);
        float wb = __ldg(we1p + hh*64 + 32 + h2);
        sP[h2*33 + hh] = 0.5f*(wa + wb);
        sQ[h2*33 + hh] = 0.5f*(wb - wa);
        sW2[h2*33 + hh] = __ldg(wn2s + idx);
    }
    __syncthreads();

    const float invD = 1.0f / __ldg(D + node);
    float s = 0.f;
    #pragma unroll
    for (int k0 = 0; k0 < FIN; k0 += 4) {
        float4 av = *(const float4*)&sAs2[w*132 + k0];
        s = fmaf(av.x, sWn[(k0+0)*33 + l], s);
        s = fmaf(av.y, sWn[(k0+1)*33 + l], s);
        s = fmaf(av.z, sWn[(k0+2)*33 + l], s);
        s = fmaf(av.w, sWn[(k0+3)*33 + l], s);
    }
    float x = fmaxf(fmaf(s, invD, __ldg(bn1p+l) + __ldg(bn1s+l)), 0.f);

    float u  = __ldg(be1p+l) + __ldg(be1s+l);
    float vv = 0.f;
    float s2 = __ldg(bn2p+l) + __ldg(bn2s+l);
    #pragma unroll
    for (int h2 = 0; h2 < 32; h2++) {
        float xx = __shfl_sync(0xffffffffu, x, h2);
        u  = fmaf(xx, sP[h2*33 + l], u);
        vv = fmaf(xx, sQ[h2*33 + l], vv);
        s2 = fmaf(xx, sW2[h2*33 + l], s2);
    }
    g_u1[node*HH + l] = u;
    g_v1[node*HH + l] = vv;
    g_s2[node*HH + l] = s2;
}

// ============================================================================
// K2' (lightweight): per block 8 nodes / 128 edges.
//   Asum1[h] = sum_j relu(u1[src]+v1[dst]+T1)  (lane h, fp32)
//   Xn2 = relu(Asum1/D @ wn2p^T + s2)  (shfl loop)
//   u2/v2 from we2p (P/Q shfl loop). NO T2 write.
// ============================================================================
__global__ __launch_bounds__(256) void k2(const int* __restrict__ dst,
                                          const float* __restrict__ D,
                                          const float* __restrict__ wn2p,
                                          const float* __restrict__ we2p,
                                          const float* __restrict__ be2p,
                                          const float* __restrict__ be2s) {
    __shared__ float sWn[32*33];
    __shared__ float sP[32*33];
    __shared__ float sQ[32*33];
    const int tid = threadIdx.x, blk = blockIdx.x;
    const int w = tid >> 5, h = tid & 31;

    #pragma unroll
    for (int r = 0; r < 4; r++) {
        int idx = tid + 256*r;
        int hh = idx >> 5, h2 = idx & 31;
        sWn[h2*33 + hh] = __ldg(wn2p + idx);
        float wa = __ldg(we2p + hh*64 + h2);
        float wb = __ldg(we2p + hh*64 + 32 + h2);
        sP[h2*33 + hh] = 0.5f*(wa + wb);
        sQ[h2*33 + hh] = 0.5f*(wb - wa);
    }

    const int node = blk*8 + w;
    const float u1h = g_u1[node*HH + h];
    const int* de = dst + node*DEGQ;
    const size_t ebase = (size_t)node*DEGQ;
    float asum = 0.f;
    #pragma unroll
    for (int j = 0; j < DEGQ; j++) {
        int d = __ldg(de + j);
        float val = u1h + g_v1[d*HH + h] + g_T[(ebase + j)*HH + h];
        asum += fmaxf(val, 0.f);
    }
    __syncthreads();

    const float invD = 1.0f / __ldg(D + node);
    float s = 0.f;
    #pragma unroll
    for (int h2 = 0; h2 < 32; h2++) {
        float aa = __shfl_sync(0xffffffffu, asum, h2);
        s = fmaf(aa, sWn[h2*33 + h], s);
    }
    float x = fmaxf(fmaf(s, invD, g_s2[node*HH + h]), 0.f);
    float u = __ldg(be2p+h) + __ldg(be2s+h), vv = 0.f;
    #pragma unroll
    for (int h2 = 0; h2 < 32; h2++) {
        float xx = __shfl_sync(0xffffffffu, x, h2);
        u  = fmaf(xx, sP[h2*33 + h], u);
        vv = fmaf(xx, sQ[h2*33 + h], vv);
    }
    g_u2[node*HH + h] = u;
    g_v2[node*HH + h] = vv;
}

// ============================================================================
// K3' (fused): per block 8 nodes / 128 edges.
//   vals1 = relu(u1[src]+v1[dst]+T1) recomputed -> bf16 split A1+A2 (smem)
//   T2 = vals1 @ we2s^T via mma.sync, fragments kept in registers;
//   classifier applied on fragments: out[e]=sigmoid(sum relu(u2+v2+T2)*wc+bc)
// ============================================================================
#define K2P 80
__global__ __launch_bounds__(256) void k3(const int* __restrict__ dst,
                                          const float* __restrict__ we2s,
                                          const float* __restrict__ wc,
                                          const float* __restrict__ bc,
                                          float* __restrict__ out) {
    __shared__ __align__(16) unsigned char sA1[128*K2P];
    __shared__ __align__(16) unsigned char sA2[128*K2P];
    __shared__ __align__(16) unsigned char sB1[32*K2P];
    __shared__ __align__(16) unsigned char sB2[32*K2P];

    const int tid = threadIdx.x, blk = blockIdx.x;
    const int w = tid >> 5, l = tid & 31;

    // ---- B convert: we2s 32x32 -> B1,B2 ----
    #pragma unroll
    for (int r = 0; r < 4; r++) {
        int idx = tid + 256*r;                  // 0..1023
        int n = idx >> 5, k = idx & 31;
        float wv = __ldg(we2s + idx);
        __nv_bfloat16 b1 = __float2bfloat16(wv);
        __nv_bfloat16 b2 = __float2bfloat16(wv - __bfloat162float(b1));
        uint32_t o = n*K2P + 2*k;
        *(__nv_bfloat16*)(sB1 + o) = b1;
        *(__nv_bfloat16*)(sB2 + o) = b2;
    }

    // ---- phase 1: vals1 recompute, split-pack via shfl, store A1/A2 ----
    const int node = blk*8 + w;
    const float u1h = g_u1[node*HH + l];
    const int* de = dst + node*DEGQ;
    const size_t ebase = (size_t)node*DEGQ;
    #pragma unroll
    for (int j = 0; j < DEGQ; j++) {
        int d = __ldg(de + j);
        float val = u1h + g_v1[d*HH + l] + g_T[(ebase + j)*HH + l];
        val = fmaxf(val, 0.f);
        __nv_bfloat16 b1 = __float2bfloat16(val);
        __nv_bfloat16 b2 = __float2bfloat16(val - __bfloat162float(b1));
        uint32_t m1 = (uint32_t)__bfloat16_as_ushort(b1);
        uint32_t m2 = (uint32_t)__bfloat16_as_ushort(b2);
        uint32_t o1 = __shfl_down_sync(0xffffffffu, m1, 1);
        uint32_t o2 = __shfl_down_sync(0xffffffffu, m2, 1);
        if (!(l & 1)) {
            const int row = w*DEGQ + j;
            *(uint32_t*)(sA1 + row*K2P + l*2) = m1 | (o1 << 16);
            *(uint32_t*)(sA2 + row*K2P + l*2) = m2 | (o2 << 16);
        }
    }
    __syncthreads();

    // ---- MMA: warp w owns rows w*16..w*16+15 (= node blk*8+w's 16 edges) ----
    float c[4][4];
    #pragma unroll
    for (int nt = 0; nt < 4; nt++)
        c[nt][0] = c[nt][1] = c[nt][2] = c[nt][3] = 0.f;
    {
        const uint32_t a1_base = smem_u32(sA1) + (uint32_t)((w*16 + (l & 15))*K2P + (l >> 4)*16);
        const uint32_t a2_base = smem_u32(sA2) + (uint32_t)((w*16 + (l & 15))*K2P + (l >> 4)*16);
        const uint32_t b1_base = smem_u32(sB1) + (uint32_t)(((l & 7))*K2P + ((l >> 3) & 1)*16);
        const uint32_t b2_base = smem_u32(sB2) + (uint32_t)(((l & 7))*K2P + ((l >> 3) & 1)*16);

        #pragma unroll
        for (int ks = 0; ks < 2; ks++) {
            const uint32_t kb = ks*32;
            uint32_t a1[4], a2[4];
            ldsm4(a1, a1_base + kb);
            ldsm4(a2, a2_base + kb);
            #pragma unroll
            for (int nt = 0; nt < 4; nt++) {
                uint32_t b1[2], b2[2];
                ldsm2(b1, b1_base + nt*8*K2P + kb);
                ldsm2(b2, b2_base + nt*8*K2P + kb);
                mma_bf16(c[nt], a1, b1);
                mma_bf16(c[nt], a1, b2);
                mma_bf16(c[nt], a2, b1);
            }
        }
    }

    // ---- fused classifier on fragments ----
    // frag: c[nt][0,1] = row r0 cols h0,h0+1 ; c[nt][2,3] = row r0+8
    const int lg = l & 3, r0 = l >> 2;
    const size_t e0 = (size_t)blk*128 + w*16 + r0;
    const size_t e1 = e0 + 8;
    const int d0 = __ldg(dst + e0);
    const int d1 = __ldg(dst + e1);
    float acc0 = 0.f, acc1 = 0.f;
    #pragma unroll
    for (int nt = 0; nt < 4; nt++) {
        const int h0 = nt*8 + lg*2;
        const float2 wcv = *(const float2*)&wc[h0];
        const float2 uu  = *(const float2*)&g_u2[node*HH + h0];
        const float2 va  = *(const float2*)&g_v2[d0*HH + h0];
        const float2 vb  = *(const float2*)&g_v2[d1*HH + h0];
        acc0 += fmaxf(uu.x + va.x + c[nt][0], 0.f) * wcv.x
              + fmaxf(uu.y + va.y + c[nt][1], 0.f) * wcv.y;
        acc1 += fmaxf(uu.x + vb.x + c[nt][2], 0.f) * wcv.x
              + fmaxf(uu.y + vb.y + c[nt][3], 0.f) * wcv.y;
    }
    acc0 += __shfl_xor_sync(0xffffffffu, acc0, 1);
    acc0 += __shfl_xor_sync(0xffffffffu, acc0, 2);
    acc1 += __shfl_xor_sync(0xffffffffu, acc1, 1);
    acc1 += __shfl_xor_sync(0xffffffffu, acc1, 2);
    if (lg == 0) {
        const float bcv = __ldg(bc);
        out[e0] = 1.f / (1.f + __expf(-(acc0 + bcv)));
        out[e1] = 1.f / (1.f + __expf(-(acc1 + bcv)));
    }
}

// ============================================================================
extern "C" void kernel_launch(void* const* d_in, const int* in_sizes, int n_in,
                              void* d_out, int out_size) {
    const float* X    = (const float*)d_in[0];
    const int*   dst  = (const int*)  d_in[2];
    const float* D    = (const float*)d_in[3];
    const float* wn1p = (const float*)d_in[4];
    const float* bn1p = (const float*)d_in[5];
    const float* bn1s = (const float*)d_in[7];
    const float* we1p = (const float*)d_in[8];
    const float* be1p = (const float*)d_in[9];
    const float* we1s = (const float*)d_in[10];
    const float* be1s = (const float*)d_in[11];
    const float* wn2p = (const float*)d_in[12];
    const float* bn2p = (const float*)d_in[13];
    const float* wn2s = (const float*)d_in[14];
    const float* bn2s = (const float*)d_in[15];
    const float* we2p = (const float*)d_in[16];
    const float* be2p = (const float*)d_in[17];
    const float* we2s = (const float*)d_in[18];
    const float* be2s = (const float*)d_in[19];
    const float* wc   = (const float*)d_in[20];
    const float* bc   = (const float*)d_in[21];
    float* out = (float*)d_out;

    cudaFuncSetAttribute(k1, cudaFuncAttributeMaxDynamicSharedMemorySize, K1_SMEM);

    k1 <<<NN/8, 256, K1_SMEM>>>(X, dst, D, we1s, wn1p, bn1p, bn1s,
                                we1p, be1p, be1s, wn2s, bn2p, bn2s);
    k2 <<<NN/8, 256>>>(dst, D, wn2p, we2p, be2p, be2s);
    k3 <<<NN/8, 256>>>(dst, we2s, wc, bc, out);
}

// round 9
// speedup vs baseline: 1.2429x; 1.0669x over previous
#include <cuda_runtime.h>
#include <cuda_bf16.h>
#include <cstdint>

#define NN   50000
#define DEGQ 16
#define EE   (NN*DEGQ)
#define HH   32
#define FIN  128

// ---------------- scratch (device globals; no allocation) ----------------
__device__ float g_T[(size_t)EE*HH];       // T1 only : 102.4MB
__device__ float g_u1[NN*HH];
__device__ float g_v1[NN*HH];
__device__ float g_s2[NN*HH];
__device__ float g_u2[NN*HH];
__device__ float g_v2[NN*HH];

// ---------------- mma.sync helpers ----------------
__device__ __forceinline__ uint32_t smem_u32(const void* p) {
    uint32_t a;
    asm("{ .reg .u64 t; cvta.to.shared.u64 t, %1; cvt.u32.u64 %0, t; }" : "=r"(a) : "l"(p));
    return a;
}
__device__ __forceinline__ void ldsm4(uint32_t* r, uint32_t addr) {
    asm volatile("ldmatrix.sync.aligned.m8n8.x4.shared.b16 {%0,%1,%2,%3}, [%4];"
        : "=r"(r[0]), "=r"(r[1]), "=r"(r[2]), "=r"(r[3]) : "r"(addr));
}
__device__ __forceinline__ void ldsm2(uint32_t* r, uint32_t addr) {
    asm volatile("ldmatrix.sync.aligned.m8n8.x2.shared.b16 {%0,%1}, [%2];"
        : "=r"(r[0]), "=r"(r[1]) : "r"(addr));
}
__device__ __forceinline__ void mma_bf16(float* c, const uint32_t* a, const uint32_t* b) {
    asm volatile("mma.sync.aligned.m16n8k16.row.col.f32.bf16.bf16.f32 "
        "{%0,%1,%2,%3}, {%4,%5,%6,%7}, {%8,%9}, {%0,%1,%2,%3};"
        : "+f"(c[0]), "+f"(c[1]), "+f"(c[2]), "+f"(c[3])
        : "r"(a[0]), "r"(a[1]), "r"(a[2]), "r"(a[3]), "r"(b[0]), "r"(b[1]));
}
__device__ __forceinline__ void bf16split(float v, __nv_bfloat16& hi, __nv_bfloat16& lo) {
    hi = __float2bfloat16(v);
    lo = __float2bfloat16(v - __bfloat162float(hi));
}

// ---- k1 smem layout. Row pitch 272B (main), 80B (tail stage-2). ----
#define PITCH    272
#define OFF_A1   0
#define OFF_A2   (128*PITCH)            // 34816
#define OFF_W1   (2*128*PITCH)          // 69632  (we1s, later wn1p)
#define OFF_W2   (OFF_W1 + 32*PITCH)    // 78336
#define K1_SMEM  (OFF_W2 + 32*PITCH)    // 87040
// tail regions (bytes, alias A1 region after main MMA)
#define TA1  0          // asum split hi : 16 x 272
#define TA2  4608       // asum split lo
#define TC1  9216       // B'' = [P;Q;wn2s] hi : 96 x 80
#define TC2  16896      // B'' lo
#define TX1  24576      // x split hi : 16 x 80
#define TX2  25856      // x split lo
#define SXO  (27136/4)  // sX floats : 8 x 34
#define SXP  34
#define TP   80         // tail stage-2 pitch

// ============================================================================
// K1: per block 8 nodes / 128 edges.
//   main: T1 = A1W1 + A1W2 + A2W1 (mma.sync) -> g_T  [round-5 proven]
//   tail (all on tensor cores now):
//     MMA1 (warp 0):  s   = Asum @ wn1p^T
//     MMA2 (warps 0-2): u1/v1/s2 = Xn1 @ {P,Q,wn2s}^T
// ============================================================================
__global__ __launch_bounds__(256, 2) void k1(const float* __restrict__ X,
                                             const int*   __restrict__ dst,
                                             const float* __restrict__ D,
                                             const float* __restrict__ we1s,
                                             const float* __restrict__ wn1p,
                                             const float* __restrict__ bn1p,
                                             const float* __restrict__ bn1s,
                                             const float* __restrict__ we1p,
                                             const float* __restrict__ be1p,
                                             const float* __restrict__ be1s,
                                             const float* __restrict__ wn2s,
                                             const float* __restrict__ bn2p,
                                             const float* __restrict__ bn2s) {
    extern __shared__ unsigned char smb[];
    float* sf = (float*)smb;
    const uint32_t sb = smem_u32(smb);

    const int tid = threadIdx.x;
    const int blk = blockIdx.x;
    const int w = tid >> 5, l = tid & 31;

    // ---- W convert: we1s (32 x 128 fp32) -> W1,W2 bf16 ----
    #pragma unroll
    for (int r = 0; r < 16; r++) {
        int idx = tid + 256*r;
        int h = idx >> 7, k = idx & 127;
        __nv_bfloat16 w1, w2;
        bf16split(__ldg(we1s + idx), w1, w2);
        uint32_t o = h*PITCH + 2*k;
        *(__nv_bfloat16*)(smb + OFF_W1 + o) = w1;
        *(__nv_bfloat16*)(smb + OFF_W2 + o) = w2;
    }

    // ---- phase B: gather, abs-diff, fp32 asum, bf16 split stores ----
    const int node = blk*8 + w;
    const float4 xv = ((const float4*)(X + (size_t)node*FIN))[l];
    float4 asum = make_float4(0.f, 0.f, 0.f, 0.f);
    const int* de = dst + node*DEGQ;
    #pragma unroll
    for (int j = 0; j < DEGQ; j++) {
        int d = __ldg(de + j);
        float4 g = ((const float4*)(X + (size_t)d*FIN))[l];
        float4 a;
        a.x = fabsf(xv.x - g.x);
        a.y = fabsf(xv.y - g.y);
        a.z = fabsf(xv.z - g.z);
        a.w = fabsf(xv.w - g.w);
        asum.x += a.x; asum.y += a.y; asum.z += a.z; asum.w += a.w;

        __nv_bfloat16 h0,h1,h2,h3,r0,r1,r2,r3;
        bf16split(a.x, h0, r0); bf16split(a.y, h1, r1);
        bf16split(a.z, h2, r2); bf16split(a.w, h3, r3);
        __nv_bfloat162 p01 = __halves2bfloat162(h0, h1);
        __nv_bfloat162 p23 = __halves2bfloat162(h2, h3);
        __nv_bfloat162 q01 = __halves2bfloat162(r0, r1);
        __nv_bfloat162 q23 = __halves2bfloat162(r2, r3);
        uint64_t hiw = (uint64_t)(*(uint32_t*)&p01) | ((uint64_t)(*(uint32_t*)&p23) << 32);
        uint64_t low = (uint64_t)(*(uint32_t*)&q01) | ((uint64_t)(*(uint32_t*)&q23) << 32);

        const int row = w*DEGQ + j;
        uint32_t o = row*PITCH + l*8;
        *(uint64_t*)(smb + OFF_A1 + o) = hiw;
        *(uint64_t*)(smb + OFF_A2 + o) = low;
    }
    __syncthreads();

    // ---- main MMA: warp w handles rows w*16..w*16+15, all 32 output cols ----
    {
        const int wr = w*16;
        float c[4][4];
        #pragma unroll
        for (int nt = 0; nt < 4; nt++)
            c[nt][0] = c[nt][1] = c[nt][2] = c[nt][3] = 0.f;

        const uint32_t a_lane_off = (uint32_t)((wr + (l & 15))*PITCH + (l >> 4)*16);
        const uint32_t b_lane_off = (uint32_t)(((l & 7))*PITCH + ((l >> 3) & 1)*16);

        #pragma unroll
        for (int ks = 0; ks < 8; ks++) {
            uint32_t kb = ks*32;
            uint32_t a1[4], a2[4];
            ldsm4(a1, sb + OFF_A1 + a_lane_off + kb);
            ldsm4(a2, sb + OFF_A2 + a_lane_off + kb);
            #pragma unroll
            for (int nt = 0; nt < 4; nt++) {
                uint32_t b1[2], b2[2];
                uint32_t bo = b_lane_off + (uint32_t)(nt*8*PITCH) + kb;
                ldsm2(b1, sb + OFF_W1 + bo);
                ldsm2(b2, sb + OFF_W2 + bo);
                mma_bf16(c[nt], a1, b1);
                mma_bf16(c[nt], a1, b2);
                mma_bf16(c[nt], a2, b1);
            }
        }

        const int r0 = l >> 2, c0 = (l & 3)*2;
        const size_t base = (size_t)blk*128 + wr;
        #pragma unroll
        for (int nt = 0; nt < 4; nt++) {
            *(float2*)&g_T[(base + r0)*HH + nt*8 + c0]     = make_float2(c[nt][0], c[nt][1]);
            *(float2*)&g_T[(base + r0 + 8)*HH + nt*8 + c0] = make_float2(c[nt][2], c[nt][3]);
        }
    }
    __syncthreads();   // main-MMA smem reads done; regions reusable

    // ================== tensor-core tail ==================
    // (a) B' = wn1p split -> W region (reuse)
    #pragma unroll
    for (int r = 0; r < 16; r++) {
        int idx = tid + 256*r;
        int h = idx >> 7, k = idx & 127;
        __nv_bfloat16 w1, w2;
        bf16split(__ldg(wn1p + idx), w1, w2);
        uint32_t o = h*PITCH + 2*k;
        *(__nv_bfloat16*)(smb + OFF_W1 + o) = w1;
        *(__nv_bfloat16*)(smb + OFF_W2 + o) = w2;
    }
    // (b) B'' = [P; Q; wn2s] (96 x 32) split, pitch 80
    #pragma unroll
    for (int r = 0; r < 12; r++) {
        int idx = tid + 256*r;                 // 0..3071
        int n = idx >> 5, k = idx & 31;
        float wv;
        if (n < 32) {
            float wa = __ldg(we1p + n*64 + k), wb = __ldg(we1p + n*64 + 32 + k);
            wv = 0.5f*(wa + wb);
        } else if (n < 64) {
            int h = n - 32;
            float wa = __ldg(we1p + h*64 + k), wb = __ldg(we1p + h*64 + 32 + k);
            wv = 0.5f*(wb - wa);
        } else {
            wv = __ldg(wn2s + (n-64)*32 + k);
        }
        __nv_bfloat16 b1, b2;
        bf16split(wv, b1, b2);
        uint32_t o = n*TP + 2*k;
        *(__nv_bfloat16*)(smb + TC1 + o) = b1;
        *(__nv_bfloat16*)(smb + TC2 + o) = b2;
    }
    // (c) asum -> TA rows 0-7 (split); zero rows 8-15
    {
        __nv_bfloat16 h0,h1,h2,h3,r0,r1,r2,r3;
        bf16split(asum.x, h0, r0); bf16split(asum.y, h1, r1);
        bf16split(asum.z, h2, r2); bf16split(asum.w, h3, r3);
        __nv_bfloat162 p01 = __halves2bfloat162(h0, h1);
        __nv_bfloat162 p23 = __halves2bfloat162(h2, h3);
        __nv_bfloat162 q01 = __halves2bfloat162(r0, r1);
        __nv_bfloat162 q23 = __halves2bfloat162(r2, r3);
        uint64_t hiw = (uint64_t)(*(uint32_t*)&p01) | ((uint64_t)(*(uint32_t*)&p23) << 32);
        uint64_t low = (uint64_t)(*(uint32_t*)&q01) | ((uint64_t)(*(uint32_t*)&q23) << 32);
        *(uint64_t*)(smb + TA1 + w*PITCH + l*8) = hiw;
        *(uint64_t*)(smb + TA2 + w*PITCH + l*8) = low;
        *(uint64_t*)(smb + TA1 + (8+w)*PITCH + l*8) = 0ull;
        *(uint64_t*)(smb + TA2 + (8+w)*PITCH + l*8) = 0ull;
    }
    __syncthreads();

    // (d) MMA1 (warp 0 only): s = Asum @ wn1p^T  -> sX
    if (w == 0) {
        float c[4][4];
        #pragma unroll
        for (int nt = 0; nt < 4; nt++)
            c[nt][0] = c[nt][1] = c[nt][2] = c[nt][3] = 0.f;
        const uint32_t a_off = (uint32_t)((l & 15)*PITCH + (l >> 4)*16);
        const uint32_t b_off = (uint32_t)((l & 7)*PITCH + ((l >> 3) & 1)*16);
        #pragma unroll
        for (int ks = 0; ks < 8; ks++) {
            uint32_t kb = ks*32;
            uint32_t a1[4], a2[4];
            ldsm4(a1, sb + TA1 + a_off + kb);
            ldsm4(a2, sb + TA2 + a_off + kb);
            #pragma unroll
            for (int nt = 0; nt < 4; nt++) {
                uint32_t b1[2], b2[2];
                uint32_t bo = b_off + (uint32_t)(nt*8*PITCH) + kb;
                ldsm2(b1, sb + OFF_W1 + bo);
                ldsm2(b2, sb + OFF_W2 + bo);
                mma_bf16(c[nt], a1, b1);
                mma_bf16(c[nt], a1, b2);
                mma_bf16(c[nt], a2, b1);
            }
        }
        const int nd = l >> 2, c0 = (l & 3)*2;
        #pragma unroll
        for (int nt = 0; nt < 4; nt++)
            *(float2*)&sf[SXO + nd*SXP + nt*8 + c0] = make_float2(c[nt][0], c[nt][1]);
    }
    __syncthreads();

    // (e) x = relu(s/D + b) -> split into TX rows 0-7; zero rows 8-15
    {
        const float invD = 1.0f / __ldg(D + node);
        float x = fmaxf(fmaf(sf[SXO + w*SXP + l], invD,
                             __ldg(bn1p+l) + __ldg(bn1s+l)), 0.f);
        __nv_bfloat16 xh, xl;
        bf16split(x, xh, xl);
        *(__nv_bfloat16*)(smb + TX1 + w*TP + 2*l) = xh;
        *(__nv_bfloat16*)(smb + TX2 + w*TP + 2*l) = xl;
        if (l < 20) {
            *(uint32_t*)(smb + TX1 + (8+w)*TP + 4*l) = 0u;
            *(uint32_t*)(smb + TX2 + (8+w)*TP + 4*l) = 0u;
        }
    }
    __syncthreads();

    // (f) MMA2 (warps 0-2): {u1, v1, s2} = Xn1 @ {P,Q,wn2s}^T
    if (w < 3) {
        float c[4][4];
        #pragma unroll
        for (int nt = 0; nt < 4; nt++)
            c[nt][0] = c[nt][1] = c[nt][2] = c[nt][3] = 0.f;
        const uint32_t a_off = (uint32_t)((l & 15)*TP + (l >> 4)*16);
        const uint32_t b_off = (uint32_t)(w*32*TP + (l & 7)*TP + ((l >> 3) & 1)*16);
        #pragma unroll
        for (int ks = 0; ks < 2; ks++) {
            uint32_t kb = ks*32;
            uint32_t a1[4], a2[4];
            ldsm4(a1, sb + TX1 + a_off + kb);
            ldsm4(a2, sb + TX2 + a_off + kb);
            #pragma unroll
            for (int nt = 0; nt < 4; nt++) {
                uint32_t b1[2], b2[2];
                uint32_t bo = b_off + (uint32_t)(nt*8*TP) + kb;
                ldsm2(b1, sb + TC1 + bo);
                ldsm2(b2, sb + TC2 + bo);
                mma_bf16(c[nt], a1, b1);
                mma_bf16(c[nt], a1, b2);
                mma_bf16(c[nt], a2, b1);
            }
        }
        const int nd = l >> 2, c0 = (l & 3)*2;
        const int onode = blk*8 + nd;
        #pragma unroll
        for (int nt = 0; nt < 4; nt++) {
            const int h0 = nt*8 + c0;
            float2 r = make_float2(c[nt][0], c[nt][1]);
            if (w == 0) {
                r.x += __ldg(be1p+h0)   + __ldg(be1s+h0);
                r.y += __ldg(be1p+h0+1) + __ldg(be1s+h0+1);
                *(float2*)&g_u1[onode*HH + h0] = r;
            } else if (w == 1) {
                *(float2*)&g_v1[onode*HH + h0] = r;
            } else {
                r.x += __ldg(bn2p+h0)   + __ldg(bn2s+h0);
                r.y += __ldg(bn2p+h0+1) + __ldg(bn2s+h0+1);
                *(float2*)&g_s2[onode*HH + h0] = r;
            }
        }
    }
}

// ============================================================================
// K2' (lightweight): Asum1 -> Xn2 -> u2/v2. NO T2 write.
// ============================================================================
__global__ __launch_bounds__(256) void k2(const int* __restrict__ dst,
                                          const float* __restrict__ D,
                                          const float* __restrict__ wn2p,
                                          const float* __restrict__ we2p,
                                          const float* __restrict__ be2p,
                                          const float* __restrict__ be2s) {
    __shared__ float sWn[32*33];
    __shared__ float sP[32*33];
    __shared__ float sQ[32*33];
    const int tid = threadIdx.x, blk = blockIdx.x;
    const int w = tid >> 5, h = tid & 31;

    #pragma unroll
    for (int r = 0; r < 4; r++) {
        int idx = tid + 256*r;
        int hh = idx >> 5, h2 = idx & 31;
        sWn[h2*33 + hh] = __ldg(wn2p + idx);
        float wa = __ldg(we2p + hh*64 + h2);
        float wb = __ldg(we2p + hh*64 + 32 + h2);
        sP[h2*33 + hh] = 0.5f*(wa + wb);
        sQ[h2*33 + hh] = 0.5f*(wb - wa);
    }

    const int node = blk*8 + w;
    const float u1h = g_u1[node*HH + h];
    const int* de = dst + node*DEGQ;
    const size_t ebase = (size_t)node*DEGQ;
    float asum = 0.f;
    #pragma unroll
    for (int j = 0; j < DEGQ; j++) {
        int d = __ldg(de + j);
        float val = u1h + g_v1[d*HH + h] + g_T[(ebase + j)*HH + h];
        asum += fmaxf(val, 0.f);
    }
    __syncthreads();

    const float invD = 1.0f / __ldg(D + node);
    float s = 0.f;
    #pragma unroll
    for (int h2 = 0; h2 < 32; h2++) {
        float aa = __shfl_sync(0xffffffffu, asum, h2);
        s = fmaf(aa, sWn[h2*33 + h], s);
    }
    float x = fmaxf(fmaf(s, invD, g_s2[node*HH + h]), 0.f);
    float u = __ldg(be2p+h) + __ldg(be2s+h), vv = 0.f;
    #pragma unroll
    for (int h2 = 0; h2 < 32; h2++) {
        float xx = __shfl_sync(0xffffffffu, x, h2);
        u  = fmaf(xx, sP[h2*33 + h], u);
        vv = fmaf(xx, sQ[h2*33 + h], vv);
    }
    g_u2[node*HH + h] = u;
    g_v2[node*HH + h] = vv;
}

// ============================================================================
// K3' (fused): vals1 recompute -> T2 MMA in registers -> classifier -> out
// ============================================================================
#define K2P 80
__global__ __launch_bounds__(256) void k3(const int* __restrict__ dst,
                                          const float* __restrict__ we2s,
                                          const float* __restrict__ wc,
                                          const float* __restrict__ bc,
                                          float* __restrict__ out) {
    __shared__ __align__(16) unsigned char sA1[128*K2P];
    __shared__ __align__(16) unsigned char sA2[128*K2P];
    __shared__ __align__(16) unsigned char sB1[32*K2P];
    __shared__ __align__(16) unsigned char sB2[32*K2P];

    const int tid = threadIdx.x, blk = blockIdx.x;
    const int w = tid >> 5, l = tid & 31;

    #pragma unroll
    for (int r = 0; r < 4; r++) {
        int idx = tid + 256*r;
        int n = idx >> 5, k = idx & 31;
        __nv_bfloat16 b1, b2;
        bf16split(__ldg(we2s + idx), b1, b2);
        uint32_t o = n*K2P + 2*k;
        *(__nv_bfloat16*)(sB1 + o) = b1;
        *(__nv_bfloat16*)(sB2 + o) = b2;
    }

    const int node = blk*8 + w;
    const float u1h = g_u1[node*HH + l];
    const int* de = dst + node*DEGQ;
    const size_t ebase = (size_t)node*DEGQ;
    #pragma unroll
    for (int j = 0; j < DEGQ; j++) {
        int d = __ldg(de + j);
        float val = u1h + g_v1[d*HH + l] + g_T[(ebase + j)*HH + l];
        val = fmaxf(val, 0.f);
        __nv_bfloat16 b1, b2;
        bf16split(val, b1, b2);
        uint32_t m1 = (uint32_t)__bfloat16_as_ushort(b1);
        uint32_t m2 = (uint32_t)__bfloat16_as_ushort(b2);
        uint32_t o1 = __shfl_down_sync(0xffffffffu, m1, 1);
        uint32_t o2 = __shfl_down_sync(0xffffffffu, m2, 1);
        if (!(l & 1)) {
            const int row = w*DEGQ + j;
            *(uint32_t*)(sA1 + row*K2P + l*2) = m1 | (o1 << 16);
            *(uint32_t*)(sA2 + row*K2P + l*2) = m2 | (o2 << 16);
        }
    }
    __syncthreads();

    float c[4][4];
    #pragma unroll
    for (int nt = 0; nt < 4; nt++)
        c[nt][0] = c[nt][1] = c[nt][2] = c[nt][3] = 0.f;
    {
        const uint32_t a1_base = smem_u32(sA1) + (uint32_t)((w*16 + (l & 15))*K2P + (l >> 4)*16);
        const uint32_t a2_base = smem_u32(sA2) + (uint32_t)((w*16 + (l & 15))*K2P + (l >> 4)*16);
        const uint32_t b1_base = smem_u32(sB1) + (uint32_t)(((l & 7))*K2P + ((l >> 3) & 1)*16);
        const uint32_t b2_base = smem_u32(sB2) + (uint32_t)(((l & 7))*K2P + ((l >> 3) & 1)*16);

        #pragma unroll
        for (int ks = 0; ks < 2; ks++) {
            const uint32_t kb = ks*32;
            uint32_t a1[4], a2[4];
            ldsm4(a1, a1_base + kb);
            ldsm4(a2, a2_base + kb);
            #pragma unroll
            for (int nt = 0; nt < 4; nt++) {
                uint32_t b1[2], b2[2];
                ldsm2(b1, b1_base + nt*8*K2P + kb);
                ldsm2(b2, b2_base + nt*8*K2P + kb);
                mma_bf16(c[nt], a1, b1);
                mma_bf16(c[nt], a1, b2);
                mma_bf16(c[nt], a2, b1);
            }
        }
    }

    const int lg = l & 3, r0 = l >> 2;
    const size_t e0 = (size_t)blk*128 + w*16 + r0;
    const size_t e1 = e0 + 8;
    const int d0 = __ldg(dst + e0);
    const int d1 = __ldg(dst + e1);
    float acc0 = 0.f, acc1 = 0.f;
    #pragma unroll
    for (int nt = 0; nt < 4; nt++) {
        const int h0 = nt*8 + lg*2;
        const float2 wcv = *(const float2*)&wc[h0];
        const float2 uu  = *(const float2*)&g_u2[node*HH + h0];
        const float2 va  = *(const float2*)&g_v2[d0*HH + h0];
        const float2 vb  = *(const float2*)&g_v2[d1*HH + h0];
        acc0 += fmaxf(uu.x + va.x + c[nt][0], 0.f) * wcv.x
              + fmaxf(uu.y + va.y + c[nt][1], 0.f) * wcv.y;
        acc1 += fmaxf(uu.x + vb.x + c[nt][2], 0.f) * wcv.x
              + fmaxf(uu.y + vb.y + c[nt][3], 0.f) * wcv.y;
    }
    acc0 += __shfl_xor_sync(0xffffffffu, acc0, 1);
    acc0 += __shfl_xor_sync(0xffffffffu, acc0, 2);
    acc1 += __shfl_xor_sync(0xffffffffu, acc1, 1);
    acc1 += __shfl_xor_sync(0xffffffffu, acc1, 2);
    if (lg == 0) {
        const float bcv = __ldg(bc);
        out[e0] = 1.f / (1.f + __expf(-(acc0 + bcv)));
        out[e1] = 1.f / (1.f + __expf(-(acc1 + bcv)));
    }
}

// ============================================================================
extern "C" void kernel_launch(void* const* d_in, const int* in_sizes, int n_in,
                              void* d_out, int out_size) {
    const float* X    = (const float*)d_in[0];
    const int*   dst  = (const int*)  d_in[2];
    const float* D    = (const float*)d_in[3];
    const float* wn1p = (const float*)d_in[4];
    const float* bn1p = (const float*)d_in[5];
    const float* bn1s = (const float*)d_in[7];
    const float* we1p = (const float*)d_in[8];
    const float* be1p = (const float*)d_in[9];
    const float* we1s = (const float*)d_in[10];
    const float* be1s = (const float*)d_in[11];
    const float* wn2p = (const float*)d_in[12];
    const float* bn2p = (const float*)d_in[13];
    const float* wn2s = (const float*)d_in[14];
    const float* bn2s = (const float*)d_in[15];
    const float* we2p = (const float*)d_in[16];
    const float* be2p = (const float*)d_in[17];
    const float* we2s = (const float*)d_in[18];
    const float* be2s = (const float*)d_in[19];
    const float* wc   = (const float*)d_in[20];
    const float* bc   = (const float*)d_in[21];
    float* out = (float*)d_out;

    cudaFuncSetAttribute(k1, cudaFuncAttributeMaxDynamicSharedMemorySize, K1_SMEM);

    k1 <<<NN/8, 256, K1_SMEM>>>(X, dst, D, we1s, wn1p, bn1p, bn1s,
                                we1p, be1p, be1s, wn2s, bn2p, bn2s);
    k2 <<<NN/8, 256>>>(dst, D, wn2p, we2p, be2p, be2s);
    k3 <<<NN/8, 256>>>(dst, we2s, wc, bc, out);
}

// round 12
// speedup vs baseline: 1.2659x; 1.0184x over previous
#include <cuda_runtime.h>
#include <cuda_bf16.h>
#include <cuda_fp16.h>
#include <cstdint>

#define NN   50000
#define DEGQ 16
#define EE   (NN*DEGQ)
#define HH   32
#define FIN  128

// ---------------- scratch (device globals; no allocation) ----------------
__device__ __half g_Th[(size_t)EE*HH];     // T1 in fp16 : 51.2MB
__device__ float g_u1[NN*HH];
__device__ float g_v1[NN*HH];
__device__ float g_s2[NN*HH];
__device__ float g_u2[NN*HH];
__device__ float g_v2[NN*HH];

// ---------------- mma.sync helpers ----------------
__device__ __forceinline__ uint32_t smem_u32(const void* p) {
    uint32_t a;
    asm("{ .reg .u64 t; cvta.to.shared.u64 t, %1; cvt.u32.u64 %0, t; }" : "=r"(a) : "l"(p));
    return a;
}
__device__ __forceinline__ void ldsm4(uint32_t* r, uint32_t addr) {
    asm volatile("ldmatrix.sync.aligned.m8n8.x4.shared.b16 {%0,%1,%2,%3}, [%4];"
        : "=r"(r[0]), "=r"(r[1]), "=r"(r[2]), "=r"(r[3]) : "r"(addr));
}
__device__ __forceinline__ void ldsm2(uint32_t* r, uint32_t addr) {
    asm volatile("ldmatrix.sync.aligned.m8n8.x2.shared.b16 {%0,%1}, [%2];"
        : "=r"(r[0]), "=r"(r[1]) : "r"(addr));
}
__device__ __forceinline__ void mma_bf16(float* c, const uint32_t* a, const uint32_t* b) {
    asm volatile("mma.sync.aligned.m16n8k16.row.col.f32.bf16.bf16.f32 "
        "{%0,%1,%2,%3}, {%4,%5,%6,%7}, {%8,%9}, {%0,%1,%2,%3};"
        : "+f"(c[0]), "+f"(c[1]), "+f"(c[2]), "+f"(c[3])
        : "r"(a[0]), "r"(a[1]), "r"(a[2]), "r"(a[3]), "r"(b[0]), "r"(b[1]));
}
__device__ __forceinline__ void bf16split(float v, __nv_bfloat16& hi, __nv_bfloat16& lo) {
    hi = __float2bfloat16(v);
    lo = __float2bfloat16(v - __bfloat162float(hi));
}

// ---- k1 smem layout. Row pitch 272B (main), 80B (tail stage-2). ----
#define PITCH    272
#define OFF_A1   0
#define OFF_A2   (128*PITCH)            // 34816
#define OFF_W1   (2*128*PITCH)          // 69632  (we1s, later wn1p)
#define OFF_W2   (OFF_W1 + 32*PITCH)    // 78336
#define K1_SMEM  (OFF_W2 + 32*PITCH)    // 87040
// tail regions (bytes, alias A1 region after main MMA)
#define TA1  0          // asum split hi : 16 x 272
#define TA2  4608       // asum split lo
#define TC1  9216       // B'' = [P;Q;wn2s] hi : 96 x 80
#define TC2  16896      // B'' lo
#define TX1  24576      // x split hi : 16 x 80
#define TX2  25856      // x split lo
#define SXO  (27136/4)  // sX floats : 8 x 34
#define SXP  34
#define TP   80         // tail stage-2 pitch

// ============================================================================
// K1: per block 8 nodes / 128 edges.
//   main: T1 = A1W1 + A1W2 + A2W1 via mma.sync (4 warps x [32 rows x 32 cols]
//         -> W fragments reused across 2 row-tiles: 1536->1024 L1 phases)
//   T1 stored fp16 -> g_Th
//   tail: MMA1 (warp 0): s = Asum @ wn1p^T ; MMA2 (warps 0-2): u1/v1/s2
// ============================================================================
__global__ __launch_bounds__(256, 2) void k1(const float* __restrict__ X,
                                             const int*   __restrict__ dst,
                                             const float* __restrict__ D,
                                             const float* __restrict__ we1s,
                                             const float* __restrict__ wn1p,
                                             const float* __restrict__ bn1p,
                                             const float* __restrict__ bn1s,
                                             const float* __restrict__ we1p,
                                             const float* __restrict__ be1p,
                                             const float* __restrict__ be1s,
                                             const float* __restrict__ wn2s,
                                             const float* __restrict__ bn2p,
                                             const float* __restrict__ bn2s) {
    extern __shared__ unsigned char smb[];
    float* sf = (float*)smb;
    const uint32_t sb = smem_u32(smb);

    const int tid = threadIdx.x;
    const int blk = blockIdx.x;
    const int w = tid >> 5, l = tid & 31;

    // ---- W convert: we1s (32 x 128 fp32) -> W1,W2 bf16 ----
    #pragma unroll
    for (int r = 0; r < 16; r++) {
        int idx = tid + 256*r;
        int h = idx >> 7, k = idx & 127;
        __nv_bfloat16 w1, w2;
        bf16split(__ldg(we1s + idx), w1, w2);
        uint32_t o = h*PITCH + 2*k;
        *(__nv_bfloat16*)(smb + OFF_W1 + o) = w1;
        *(__nv_bfloat16*)(smb + OFF_W2 + o) = w2;
    }

    // ---- phase B: gather, abs-diff, fp32 asum, bf16 split stores ----
    const int node = blk*8 + w;
    const float4 xv = ((const float4*)(X + (size_t)node*FIN))[l];
    float4 asum = make_float4(0.f, 0.f, 0.f, 0.f);
    const int* de = dst + node*DEGQ;
    #pragma unroll
    for (int j = 0; j < DEGQ; j++) {
        int d = __ldg(de + j);
        float4 g = ((const float4*)(X + (size_t)d*FIN))[l];
        float4 a;
        a.x = fabsf(xv.x - g.x);
        a.y = fabsf(xv.y - g.y);
        a.z = fabsf(xv.z - g.z);
        a.w = fabsf(xv.w - g.w);
        asum.x += a.x; asum.y += a.y; asum.z += a.z; asum.w += a.w;

        __nv_bfloat16 h0,h1,h2,h3,r0,r1,r2,r3;
        bf16split(a.x, h0, r0); bf16split(a.y, h1, r1);
        bf16split(a.z, h2, r2); bf16split(a.w, h3, r3);
        __nv_bfloat162 p01 = __halves2bfloat162(h0, h1);
        __nv_bfloat162 p23 = __halves2bfloat162(h2, h3);
        __nv_bfloat162 q01 = __halves2bfloat162(r0, r1);
        __nv_bfloat162 q23 = __halves2bfloat162(r2, r3);
        uint64_t hiw = (uint64_t)(*(uint32_t*)&p01) | ((uint64_t)(*(uint32_t*)&p23) << 32);
        uint64_t low = (uint64_t)(*(uint32_t*)&q01) | ((uint64_t)(*(uint32_t*)&q23) << 32);

        const int row = w*DEGQ + j;
        uint32_t o = row*PITCH + l*8;
        *(uint64_t*)(smb + OFF_A1 + o) = hiw;
        *(uint64_t*)(smb + OFF_A2 + o) = low;
    }
    __syncthreads();

    // ---- main MMA: 4 warps, warp w -> rows 32w..32w+31, all 32 cols ----
    if (w < 4) {
        const int wr = w*32;
        float c[2][4][4];
        #pragma unroll
        for (int t = 0; t < 2; t++)
            #pragma unroll
            for (int nt = 0; nt < 4; nt++)
                c[t][nt][0] = c[t][nt][1] = c[t][nt][2] = c[t][nt][3] = 0.f;

        const uint32_t a_off = (uint32_t)((wr + (l & 15))*PITCH + (l >> 4)*16);
        const uint32_t b_off = (uint32_t)(((l & 7))*PITCH + ((l >> 3) & 1)*16);

        #pragma unroll
        for (int ks = 0; ks < 8; ks++) {
            const uint32_t kb = ks*32;
            uint32_t bfr[4][2][2];
            #pragma unroll
            for (int nt = 0; nt < 4; nt++) {
                const uint32_t bo = b_off + (uint32_t)(nt*8*PITCH) + kb;
                ldsm2(bfr[nt][0], sb + OFF_W1 + bo);
                ldsm2(bfr[nt][1], sb + OFF_W2 + bo);
            }
            #pragma unroll
            for (int t = 0; t < 2; t++) {
                uint32_t a1[4], a2[4];
                ldsm4(a1, sb + OFF_A1 + a_off + (uint32_t)(t*16*PITCH) + kb);
                ldsm4(a2, sb + OFF_A2 + a_off + (uint32_t)(t*16*PITCH) + kb);
                #pragma unroll
                for (int nt = 0; nt < 4; nt++) {
                    mma_bf16(c[t][nt], a1, bfr[nt][0]);
                    mma_bf16(c[t][nt], a1, bfr[nt][1]);
                    mma_bf16(c[t][nt], a2, bfr[nt][0]);
                }
            }
        }

        // epilogue: fp16 T1
        const int r0 = l >> 2, c0 = (l & 3)*2;
        #pragma unroll
        for (int t = 0; t < 2; t++) {
            const size_t base = (size_t)blk*128 + wr + t*16;
            #pragma unroll
            for (int nt = 0; nt < 4; nt++) {
                __half2 h01 = __floats2half2_rn(c[t][nt][0], c[t][nt][1]);
                __half2 h23 = __floats2half2_rn(c[t][nt][2], c[t][nt][3]);
                *(__half2*)&g_Th[(base + r0)*HH + nt*8 + c0]     = h01;
                *(__half2*)&g_Th[(base + r0 + 8)*HH + nt*8 + c0] = h23;
            }
        }
    }
    __syncthreads();   // main-MMA smem reads done; regions reusable

    // ================== tensor-core tail ==================
    // (a) B' = wn1p split -> W region (reuse)
    #pragma unroll
    for (int r = 0; r < 16; r++) {
        int idx = tid + 256*r;
        int h = idx >> 7, k = idx & 127;
        __nv_bfloat16 w1, w2;
        bf16split(__ldg(wn1p + idx), w1, w2);
        uint32_t o = h*PITCH + 2*k;
        *(__nv_bfloat16*)(smb + OFF_W1 + o) = w1;
        *(__nv_bfloat16*)(smb + OFF_W2 + o) = w2;
    }
    // (b) B'' = [P; Q; wn2s] (96 x 32) split, pitch 80
    #pragma unroll
    for (int r = 0; r < 12; r++) {
        int idx = tid + 256*r;                 // 0..3071
        int n = idx >> 5, k = idx & 31;
        float wv;
        if (n < 32) {
            float wa = __ldg(we1p + n*64 + k), wb = __ldg(we1p + n*64 + 32 + k);
            wv = 0.5f*(wa + wb);
        } else if (n < 64) {
            int h = n - 32;
            float wa = __ldg(we1p + h*64 + k), wb = __ldg(we1p + h*64 + 32 + k);
            wv = 0.5f*(wb - wa);
        } else {
            wv = __ldg(wn2s + (n-64)*32 + k);
        }
        __nv_bfloat16 b1, b2;
        bf16split(wv, b1, b2);
        uint32_t o = n*TP + 2*k;
        *(__nv_bfloat16*)(smb + TC1 + o) = b1;
        *(__nv_bfloat16*)(smb + TC2 + o) = b2;
    }
    // (c) asum -> TA rows 0-7 (split); zero rows 8-15
    {
        __nv_bfloat16 h0,h1,h2,h3,r0,r1,r2,r3;
        bf16split(asum.x, h0, r0); bf16split(asum.y, h1, r1);
        bf16split(asum.z, h2, r2); bf16split(asum.w, h3, r3);
        __nv_bfloat162 p01 = __halves2bfloat162(h0, h1);
        __nv_bfloat162 p23 = __halves2bfloat162(h2, h3);
        __nv_bfloat162 q01 = __halves2bfloat162(r0, r1);
        __nv_bfloat162 q23 = __halves2bfloat162(r2, r3);
        uint64_t hiw = (uint64_t)(*(uint32_t*)&p01) | ((uint64_t)(*(uint32_t*)&p23) << 32);
        uint64_t low = (uint64_t)(*(uint32_t*)&q01) | ((uint64_t)(*(uint32_t*)&q23) << 32);
        *(uint64_t*)(smb + TA1 + w*PITCH + l*8) = hiw;
        *(uint64_t*)(smb + TA2 + w*PITCH + l*8) = low;
        *(uint64_t*)(smb + TA1 + (8+w)*PITCH + l*8) = 0ull;
        *(uint64_t*)(smb + TA2 + (8+w)*PITCH + l*8) = 0ull;
    }
    __syncthreads();

    // (d) MMA1 (warp 0 only): s = Asum @ wn1p^T  -> sX
    if (w == 0) {
        float c[4][4];
        #pragma unroll
        for (int nt = 0; nt < 4; nt++)
            c[nt][0] = c[nt][1] = c[nt][2] = c[nt][3] = 0.f;
        const uint32_t a_off = (uint32_t)((l & 15)*PITCH + (l >> 4)*16);
        const uint32_t b_off = (uint32_t)((l & 7)*PITCH + ((l >> 3) & 1)*16);
        #pragma unroll
        for (int ks = 0; ks < 8; ks++) {
            uint32_t kb = ks*32;
            uint32_t a1[4], a2[4];
            ldsm4(a1, sb + TA1 + a_off + kb);
            ldsm4(a2, sb + TA2 + a_off + kb);
            #pragma unroll
            for (int nt = 0; nt < 4; nt++) {
                uint32_t b1[2], b2[2];
                uint32_t bo = b_off + (uint32_t)(nt*8*PITCH) + kb;
                ldsm2(b1, sb + OFF_W1 + bo);
                ldsm2(b2, sb + OFF_W2 + bo);
                mma_bf16(c[nt], a1, b1);
                mma_bf16(c[nt], a1, b2);
                mma_bf16(c[nt], a2, b1);
            }
        }
        const int nd = l >> 2, c0 = (l & 3)*2;
        #pragma unroll
        for (int nt = 0; nt < 4; nt++)
            *(float2*)&sf[SXO + nd*SXP + nt*8 + c0] = make_float2(c[nt][0], c[nt][1]);
    }
    __syncthreads();

    // (e) x = relu(s/D + b) -> split into TX rows 0-7; zero rows 8-15
    {
        const float invD = 1.0f / __ldg(D + node);
        float x = fmaxf(fmaf(sf[SXO + w*SXP + l], invD,
                             __ldg(bn1p+l) + __ldg(bn1s+l)), 0.f);
        __nv_bfloat16 xh, xl;
        bf16split(x, xh, xl);
        *(__nv_bfloat16*)(smb + TX1 + w*TP + 2*l) = xh;
        *(__nv_bfloat16*)(smb + TX2 + w*TP + 2*l) = xl;
        if (l < 20) {
            *(uint32_t*)(smb + TX1 + (8+w)*TP + 4*l) = 0u;
            *(uint32_t*)(smb + TX2 + (8+w)*TP + 4*l) = 0u;
        }
    }
    __syncthreads();

    // (f) MMA2 (warps 0-2): {u1, v1, s2} = Xn1 @ {P,Q,wn2s}^T
    if (w < 3) {
        float c[4][4];
        #pragma unroll
        for (int nt = 0; nt < 4; nt++)
            c[nt][0] = c[nt][1] = c[nt][2] = c[nt][3] = 0.f;
        const uint32_t a_off = (uint32_t)((l & 15)*TP + (l >> 4)*16);
        const uint32_t b_off = (uint32_t)(w*32*TP + (l & 7)*TP + ((l >> 3) & 1)*16);
        #pragma unroll
        for (int ks = 0; ks < 2; ks++) {
            uint32_t kb = ks*32;
            uint32_t a1[4], a2[4];
            ldsm4(a1, sb + TX1 + a_off + kb);
            ldsm4(a2, sb + TX2 + a_off + kb);
            #pragma unroll
            for (int nt = 0; nt < 4; nt++) {
                uint32_t b1[2], b2[2];
                uint32_t bo = b_off + (uint32_t)(nt*8*TP) + kb;
                ldsm2(b1, sb + TC1 + bo);
                ldsm2(b2, sb + TC2 + bo);
                mma_bf16(c[nt], a1, b1);
                mma_bf16(c[nt], a1, b2);
                mma_bf16(c[nt], a2, b1);
            }
        }
        const int nd = l >> 2, c0 = (l & 3)*2;
        const int onode = blk*8 + nd;
        #pragma unroll
        for (int nt = 0; nt < 4; nt++) {
            const int h0 = nt*8 + c0;
            float2 r = make_float2(c[nt][0], c[nt][1]);
            if (w == 0) {
                r.x += __ldg(be1p+h0)   + __ldg(be1s+h0);
                r.y += __ldg(be1p+h0+1) + __ldg(be1s+h0+1);
                *(float2*)&g_u1[onode*HH + h0] = r;
            } else if (w == 1) {
                *(float2*)&g_v1[onode*HH + h0] = r;
            } else {
                r.x += __ldg(bn2p+h0)   + __ldg(bn2s+h0);
                r.y += __ldg(bn2p+h0+1) + __ldg(bn2s+h0+1);
                *(float2*)&g_s2[onode*HH + h0] = r;
            }
        }
    }
}

// ============================================================================
// K2' (lightweight): Asum1 -> Xn2 -> u2/v2. NO T2 write. (T1 read as fp16)
// ============================================================================
__global__ __launch_bounds__(256) void k2(const int* __restrict__ dst,
                                          const float* __restrict__ D,
                                          const float* __restrict__ wn2p,
                                          const float* __restrict__ we2p,
                                          const float* __restrict__ be2p,
                                          const float* __restrict__ be2s) {
    __shared__ float sWn[32*33];
    __shared__ float sP[32*33];
    __shared__ float sQ[32*33];
    const int tid = threadIdx.x, blk = blockIdx.x;
    const int w = tid >> 5, h = tid & 31;

    #pragma unroll
    for (int r = 0; r < 4; r++) {
        int idx = tid + 256*r;
        int hh = idx >> 5, h2 = idx & 31;
        sWn[h2*33 + hh] = __ldg(wn2p + idx);
        float wa = __ldg(we2p + hh*64 + h2);
        float wb = __ldg(we2p + hh*64 + 32 + h2);
        sP[h2*33 + hh] = 0.5f*(wa + wb);
        sQ[h2*33 + hh] = 0.5f*(wb - wa);
    }

    const int node = blk*8 + w;
    const float u1h = g_u1[node*HH + h];
    const int* de = dst + node*DEGQ;
    const size_t ebase = (size_t)node*DEGQ;
    float asum = 0.f;
    #pragma unroll
    for (int j = 0; j < DEGQ; j++) {
        int d = __ldg(de + j);
        float val = u1h + g_v1[d*HH + h] + __half2float(g_Th[(ebase + j)*HH + h]);
        asum += fmaxf(val, 0.f);
    }
    __syncthreads();

    const float invD = 1.0f / __ldg(D + node);
    float s = 0.f;
    #pragma unroll
    for (int h2 = 0; h2 < 32; h2++) {
        float aa = __shfl_sync(0xffffffffu, asum, h2);
        s = fmaf(aa, sWn[h2*33 + h], s);
    }
    float x = fmaxf(fmaf(s, invD, g_s2[node*HH + h]), 0.f);
    float u = __ldg(be2p+h) + __ldg(be2s+h), vv = 0.f;
    #pragma unroll
    for (int h2 = 0; h2 < 32; h2++) {
        float xx = __shfl_sync(0xffffffffu, x, h2);
        u  = fmaf(xx, sP[h2*33 + h], u);
        vv = fmaf(xx, sQ[h2*33 + h], vv);
    }
    g_u2[node*HH + h] = u;
    g_v2[node*HH + h] = vv;
}

// ============================================================================
// K3' (fused): vals1 recompute (fp16 T1) -> T2 MMA in regs -> classifier
// ============================================================================
#define K2P 80
__global__ __launch_bounds__(256) void k3(const int* __restrict__ dst,
                                          const float* __restrict__ we2s,
                                          const float* __restrict__ wc,
                                          const float* __restrict__ bc,
                                          float* __restrict__ out) {
    __shared__ __align__(16) unsigned char sA1[128*K2P];
    __shared__ __align__(16) unsigned char sA2[128*K2P];
    __shared__ __align__(16) unsigned char sB1[32*K2P];
    __shared__ __align__(16) unsigned char sB2[32*K2P];

    const int tid = threadIdx.x, blk = blockIdx.x;
    const int w = tid >> 5, l = tid & 31;

    #pragma unroll
    for (int r = 0; r < 4; r++) {
        int idx = tid + 256*r;
        int n = idx >> 5, k = idx & 31;
        __nv_bfloat16 b1, b2;
        bf16split(__ldg(we2s + idx), b1, b2);
        uint32_t o = n*K2P + 2*k;
        *(__nv_bfloat16*)(sB1 + o) = b1;
        *(__nv_bfloat16*)(sB2 + o) = b2;
    }

    const int node = blk*8 + w;
    const float u1h = g_u1[node*HH + l];
    const int* de = dst + node*DEGQ;
    const size_t ebase = (size_t)node*DEGQ;
    #pragma unroll
    for (int j = 0; j < DEGQ; j++) {
        int d = __ldg(de + j);
        float val = u1h + g_v1[d*HH + l] + __half2float(g_Th[(ebase + j)*HH + l]);
        val = fmaxf(val, 0.f);
        __nv_bfloat16 b1, b2;
        bf16split(val, b1, b2);
        uint32_t m1 = (uint32_t)__bfloat16_as_ushort(b1);
        uint32_t m2 = (uint32_t)__bfloat16_as_ushort(b2);
        uint32_t o1 = __shfl_down_sync(0xffffffffu, m1, 1);
        uint32_t o2 = __shfl_down_sync(0xffffffffu, m2, 1);
        if (!(l & 1)) {
            const int row = w*DEGQ + j;
            *(uint32_t*)(sA1 + row*K2P + l*2) = m1 | (o1 << 16);
            *(uint32_t*)(sA2 + row*K2P + l*2) = m2 | (o2 << 16);
        }
    }
    __syncthreads();

    float c[4][4];
    #pragma unroll
    for (int nt = 0; nt < 4; nt++)
        c[nt][0] = c[nt][1] = c[nt][2] = c[nt][3] = 0.f;
    {
        const uint32_t a1_base = smem_u32(sA1) + (uint32_t)((w*16 + (l & 15))*K2P + (l >> 4)*16);
        const uint32_t a2_base = smem_u32(sA2) + (uint32_t)((w*16 + (l & 15))*K2P + (l >> 4)*16);
        const uint32_t b1_base = smem_u32(sB1) + (uint32_t)(((l & 7))*K2P + ((l >> 3) & 1)*16);
        const uint32_t b2_base = smem_u32(sB2) + (uint32_t)(((l & 7))*K2P + ((l >> 3) & 1)*16);

        #pragma unroll
        for (int ks = 0; ks < 2; ks++) {
            const uint32_t kb = ks*32;
            uint32_t a1[4], a2[4];
            ldsm4(a1, a1_base + kb);
            ldsm4(a2, a2_base + kb);
            #pragma unroll
            for (int nt = 0; nt < 4; nt++) {
                uint32_t b1[2], b2[2];
                ldsm2(b1, b1_base + nt*8*K2P + kb);
                ldsm2(b2, b2_base + nt*8*K2P + kb);
                mma_bf16(c[nt], a1, b1);
                mma_bf16(c[nt], a1, b2);
                mma_bf16(c[nt], a2, b1);
            }
        }
    }

    const int lg = l & 3, r0 = l >> 2;
    const size_t e0 = (size_t)blk*128 + w*16 + r0;
    const size_t e1 = e0 + 8;
    const int d0 = __ldg(dst + e0);
    const int d1 = __ldg(dst + e1);
    float acc0 = 0.f, acc1 = 0.f;
    #pragma unroll
    for (int nt = 0; nt < 4; nt++) {
        const int h0 = nt*8 + lg*2;
        const float2 wcv = *(const float2*)&wc[h0];
        const float2 uu  = *(const float2*)&g_u2[node*HH + h0];
        const float2 va  = *(const float2*)&g_v2[d0*HH + h0];
        const float2 vb  = *(const float2*)&g_v2[d1*HH + h0];
        acc0 += fmaxf(uu.x + va.x + c[nt][0], 0.f) * wcv.x
              + fmaxf(uu.y + va.y + c[nt][1], 0.f) * wcv.y;
        acc1 += fmaxf(uu.x + vb.x + c[nt][2], 0.f) * wcv.x
              + fmaxf(uu.y + vb.y + c[nt][3], 0.f) * wcv.y;
    }
    acc0 += __shfl_xor_sync(0xffffffffu, acc0, 1);
    acc0 += __shfl_xor_sync(0xffffffffu, acc0, 2);
    acc1 += __shfl_xor_sync(0xffffffffu, acc1, 1);
    acc1 += __shfl_xor_sync(0xffffffffu, acc1, 2);
    if (lg == 0) {
        const float bcv = __ldg(bc);
        out[e0] = 1.f / (1.f + __expf(-(acc0 + bcv)));
        out[e1] = 1.f / (1.f + __expf(-(acc1 + bcv)));
    }
}

// ============================================================================
extern "C" void kernel_launch(void* const* d_in, const int* in_sizes, int n_in,
                              void* d_out, int out_size) {
    const float* X    = (const float*)d_in[0];
    const int*   dst  = (const int*)  d_in[2];
    const float* D    = (const float*)d_in[3];
    const float* wn1p = (const float*)d_in[4];
    const float* bn1p = (const float*)d_in[5];
    const float* bn1s = (const float*)d_in[7];
    const float* we1p = (const float*)d_in[8];
    const float* be1p = (const float*)d_in[9];
    const float* we1s = (const float*)d_in[10];
    const float* be1s = (const float*)d_in[11];
    const float* wn2p = (const float*)d_in[12];
    const float* bn2p = (const float*)d_in[13];
    const float* wn2s = (const float*)d_in[14];
    const float* bn2s = (const float*)d_in[15];
    const float* we2p = (const float*)d_in[16];
    const float* be2p = (const float*)d_in[17];
    const float* we2s = (const float*)d_in[18];
    const float* be2s = (const float*)d_in[19];
    const float* wc   = (const float*)d_in[20];
    const float* bc   = (const float*)d_in[21];
    float* out = (float*)d_out;

    cudaFuncSetAttribute(k1, cudaFuncAttributeMaxDynamicSharedMemorySize, K1_SMEM);

    k1 <<<NN/8, 256, K1_SMEM>>>(X, dst, D, we1s, wn1p, bn1p, bn1s,
                                we1p, be1p, be1s, wn2s, bn2p, bn2s);
    k2 <<<NN/8, 256>>>(dst, D, wn2p, we2p, be2p, be2s);
    k3 <<<NN/8, 256>>>(dst, we2s, wc, bc, out);
}

// round 13
// speedup vs baseline: 1.2923x; 1.0209x over previous
#include <cuda_runtime.h>
#include <cuda_bf16.h>
#include <cuda_fp16.h>
#include <cstdint>

#define NN   50000
#define DEGQ 16
#define EE   (NN*DEGQ)
#define HH   32
#define FIN  128

// ---------------- scratch (device globals; no allocation) ----------------
__device__ __half g_Th[(size_t)EE*HH];     // T1 in fp16 : 51.2MB
__device__ float g_u1[NN*HH];
__device__ float g_v1[NN*HH];
__device__ float g_s2[NN*HH];
__device__ float g_u2[NN*HH];
__device__ float g_v2[NN*HH];

// ---------------- mma.sync helpers ----------------
__device__ __forceinline__ uint32_t smem_u32(const void* p) {
    uint32_t a;
    asm("{ .reg .u64 t; cvta.to.shared.u64 t, %1; cvt.u32.u64 %0, t; }" : "=r"(a) : "l"(p));
    return a;
}
__device__ __forceinline__ void ldsm4(uint32_t* r, uint32_t addr) {
    asm volatile("ldmatrix.sync.aligned.m8n8.x4.shared.b16 {%0,%1,%2,%3}, [%4];"
        : "=r"(r[0]), "=r"(r[1]), "=r"(r[2]), "=r"(r[3]) : "r"(addr));
}
__device__ __forceinline__ void ldsm2(uint32_t* r, uint32_t addr) {
    asm volatile("ldmatrix.sync.aligned.m8n8.x2.shared.b16 {%0,%1}, [%2];"
        : "=r"(r[0]), "=r"(r[1]) : "r"(addr));
}
__device__ __forceinline__ void mma_bf16(float* c, const uint32_t* a, const uint32_t* b) {
    asm volatile("mma.sync.aligned.m16n8k16.row.col.f32.bf16.bf16.f32 "
        "{%0,%1,%2,%3}, {%4,%5,%6,%7}, {%8,%9}, {%0,%1,%2,%3};"
        : "+f"(c[0]), "+f"(c[1]), "+f"(c[2]), "+f"(c[3])
        : "r"(a[0]), "r"(a[1]), "r"(a[2]), "r"(a[3]), "r"(b[0]), "r"(b[1]));
}
__device__ __forceinline__ void bf16split(float v, __nv_bfloat16& hi, __nv_bfloat16& lo) {
    hi = __float2bfloat16(v);
    lo = __float2bfloat16(v - __bfloat162float(hi));
}
// pack two floats to bf16x2 (lo in bits 0-15, hi in bits 16-31)
__device__ __forceinline__ uint32_t cvt2bf(float lo, float hi) {
    uint32_t r;
    asm("cvt.rn.bf16x2.f32 %0, %1, %2;" : "=r"(r) : "f"(hi), "f"(lo));
    return r;
}

// ---- k1 smem layout (bytes). Main pitch 272; tail stage-2 pitch 80. ----
#define PITCH    272
#define OFF_A1   0
#define OFF_A2   34816
#define OFF_W1   69632                  // we1s, later wn1p (restaged)
#define OFF_W2   78336
#define OFF_TA1  87040                  // dedicated: asum split hi, 16 x 272
#define OFF_TA2  91392
#define K1_SMEM  95744                  // 2 CTAs/SM (191.5KB of 228KB)
// tail aliases inside the A1 region (free after main MMA):
#define TC1  0                          // B'' = [P;Q;wn2s] hi : 96 x 80
#define TC2  7680
#define TX1  15360                      // x split hi : 16 x 80
#define TX2  16640
#define SXO  (17920/4)                  // sX floats : 8 x 34
#define SXP  34
#define TP   80

// ============================================================================
// K1: per block 8 nodes / 128 edges.
//   warps 0-3: main MMA  T1 = A1W1 + A1W2 + A2W1 -> g_Th (fp16)
//   warps 4-7 (concurrent): prefetch wn1p + [P;Q;wn2s] into registers
//   tail: MMA1 (warp 0): s = Asum @ wn1p^T ; MMA2 (warps 0-2): u1/v1/s2
// ============================================================================
__global__ __launch_bounds__(256, 2) void k1(const float* __restrict__ X,
                                             const int*   __restrict__ dst,
                                             const float* __restrict__ D,
                                             const float* __restrict__ we1s,
                                             const float* __restrict__ wn1p,
                                             const float* __restrict__ bn1p,
                                             const float* __restrict__ bn1s,
                                             const float* __restrict__ we1p,
                                             const float* __restrict__ be1p,
                                             const float* __restrict__ be1s,
                                             const float* __restrict__ wn2s,
                                             const float* __restrict__ bn2p,
                                             const float* __restrict__ bn2s) {
    extern __shared__ unsigned char smb[];
    float* sf = (float*)smb;
    const uint32_t sb = smem_u32(smb);

    const int tid = threadIdx.x;
    const int blk = blockIdx.x;
    const int w = tid >> 5, l = tid & 31;

    // ---- phase A: we1s (32 x 128 fp32) -> W1,W2 bf16 ----
    #pragma unroll
    for (int r = 0; r < 16; r++) {
        int idx = tid + 256*r;
        int h = idx >> 7, k = idx & 127;
        __nv_bfloat16 w1, w2;
        bf16split(__ldg(we1s + idx), w1, w2);
        uint32_t o = h*PITCH + 2*k;
        *(__nv_bfloat16*)(smb + OFF_W1 + o) = w1;
        *(__nv_bfloat16*)(smb + OFF_W2 + o) = w2;
    }

    // ---- phase B: gather, abs-diff, fp32 asum, bf16 split stores ----
    const int node = blk*8 + w;
    const float4 xv = ((const float4*)(X + (size_t)node*FIN))[l];
    float4 asum = make_float4(0.f, 0.f, 0.f, 0.f);
    const int* de = dst + node*DEGQ;
    #pragma unroll
    for (int j = 0; j < DEGQ; j++) {
        int d = __ldg(de + j);
        float4 g = ((const float4*)(X + (size_t)d*FIN))[l];
        float4 a;
        a.x = fabsf(xv.x - g.x);
        a.y = fabsf(xv.y - g.y);
        a.z = fabsf(xv.z - g.z);
        a.w = fabsf(xv.w - g.w);
        asum.x += a.x; asum.y += a.y; asum.z += a.z; asum.w += a.w;

        uint32_t p01 = cvt2bf(a.x, a.y);
        uint32_t p23 = cvt2bf(a.z, a.w);
        float hx = __uint_as_float(p01 << 16);
        float hy = __uint_as_float(p01 & 0xFFFF0000u);
        float hz = __uint_as_float(p23 << 16);
        float hw = __uint_as_float(p23 & 0xFFFF0000u);
        uint32_t q01 = cvt2bf(a.x - hx, a.y - hy);
        uint32_t q23 = cvt2bf(a.z - hz, a.w - hw);
        uint64_t hiw = (uint64_t)p01 | ((uint64_t)p23 << 32);
        uint64_t low = (uint64_t)q01 | ((uint64_t)q23 << 32);

        const int row = w*DEGQ + j;
        uint32_t o = row*PITCH + l*8;
        *(uint64_t*)(smb + OFF_A1 + o) = hiw;
        *(uint64_t*)(smb + OFF_A2 + o) = low;
    }

    // ---- asum -> dedicated TA (rows 0-7 data, rows 8-15 zero) ----
    {
        uint32_t p01 = cvt2bf(asum.x, asum.y);
        uint32_t p23 = cvt2bf(asum.z, asum.w);
        float hx = __uint_as_float(p01 << 16);
        float hy = __uint_as_float(p01 & 0xFFFF0000u);
        float hz = __uint_as_float(p23 << 16);
        float hw = __uint_as_float(p23 & 0xFFFF0000u);
        uint32_t q01 = cvt2bf(asum.x - hx, asum.y - hy);
        uint32_t q23 = cvt2bf(asum.z - hz, asum.w - hw);
        uint64_t hiw = (uint64_t)p01 | ((uint64_t)p23 << 32);
        uint64_t low = (uint64_t)q01 | ((uint64_t)q23 << 32);
        *(uint64_t*)(smb + OFF_TA1 + w*PITCH + l*8) = hiw;
        *(uint64_t*)(smb + OFF_TA2 + w*PITCH + l*8) = low;
        *(uint64_t*)(smb + OFF_TA1 + (8+w)*PITCH + l*8) = 0ull;
        *(uint64_t*)(smb + OFF_TA2 + (8+w)*PITCH + l*8) = 0ull;
    }
    __syncthreads();                               // ---- sync 1 ----

    // registers for the warp-4..7 prefetch path (dead on warps 0-3)
    float wreg[32];
    float breg[24];

    if (w < 4) {
        // ---- main MMA: warp w -> rows 32w..32w+31, all 32 cols ----
        const int wr = w*32;
        float c[2][4][4];
        #pragma unroll
        for (int t = 0; t < 2; t++)
            #pragma unroll
            for (int nt = 0; nt < 4; nt++)
                c[t][nt][0] = c[t][nt][1] = c[t][nt][2] = c[t][nt][3] = 0.f;

        const uint32_t a_off = (uint32_t)((wr + (l & 15))*PITCH + (l >> 4)*16);
        const uint32_t b_off = (uint32_t)(((l & 7))*PITCH + ((l >> 3) & 1)*16);

        #pragma unroll
        for (int ks = 0; ks < 8; ks++) {
            const uint32_t kb = ks*32;
            uint32_t bfr[4][2][2];
            #pragma unroll
            for (int nt = 0; nt < 4; nt++) {
                const uint32_t bo = b_off + (uint32_t)(nt*8*PITCH) + kb;
                ldsm2(bfr[nt][0], sb + OFF_W1 + bo);
                ldsm2(bfr[nt][1], sb + OFF_W2 + bo);
            }
            #pragma unroll
            for (int t = 0; t < 2; t++) {
                uint32_t a1[4], a2[4];
                ldsm4(a1, sb + OFF_A1 + a_off + (uint32_t)(t*16*PITCH) + kb);
                ldsm4(a2, sb + OFF_A2 + a_off + (uint32_t)(t*16*PITCH) + kb);
                #pragma unroll
                for (int nt = 0; nt < 4; nt++) {
                    mma_bf16(c[t][nt], a1, bfr[nt][0]);
                    mma_bf16(c[t][nt], a1, bfr[nt][1]);
                    mma_bf16(c[t][nt], a2, bfr[nt][0]);
                }
            }
        }

        // epilogue: fp16 T1
        const int r0 = l >> 2, c0 = (l & 3)*2;
        #pragma unroll
        for (int t = 0; t < 2; t++) {
            const size_t base = (size_t)blk*128 + wr + t*16;
            #pragma unroll
            for (int nt = 0; nt < 4; nt++) {
                __half2 h01 = __floats2half2_rn(c[t][nt][0], c[t][nt][1]);
                __half2 h23 = __floats2half2_rn(c[t][nt][2], c[t][nt][3]);
                *(__half2*)&g_Th[(base + r0)*HH + nt*8 + c0]     = h01;
                *(__half2*)&g_Th[(base + r0 + 8)*HH + nt*8 + c0] = h23;
            }
        }
    } else {
        // ---- concurrent prefetch (hidden under main MMA) ----
        const int ltid = tid - 128;                // 0..127
        #pragma unroll
        for (int r = 0; r < 32; r++)
            wreg[r] = __ldg(wn1p + ltid + 128*r);  // row r, col ltid
        const int cgrp = ltid >> 5, kk = ltid & 31;
        #pragma unroll
        for (int r = 0; r < 8; r++) {              // n = 4r+cgrp in [0,32): P
            int n = 4*r + cgrp;
            float wa = __ldg(we1p + n*64 + kk), wb = __ldg(we1p + n*64 + 32 + kk);
            breg[r] = 0.5f*(wa + wb);
        }
        #pragma unroll
        for (int r = 8; r < 16; r++) {             // n in [32,64): Q
            int h = 4*(r-8) + cgrp;
            float wa = __ldg(we1p + h*64 + kk), wb = __ldg(we1p + h*64 + 32 + kk);
            breg[r] = 0.5f*(wb - wa);
        }
        #pragma unroll
        for (int r = 16; r < 24; r++) {            // n in [64,96): wn2s
            int h = 4*(r-16) + cgrp;
            breg[r] = __ldg(wn2s + h*32 + kk);
        }
    }
    __syncthreads();                               // ---- sync 2 ----

    // ---- stage weights from registers (warps 4-7; STS only) ----
    if (w >= 4) {
        const int ltid = tid - 128;
        #pragma unroll
        for (int r = 0; r < 32; r++) {
            __nv_bfloat16 w1, w2;
            bf16split(wreg[r], w1, w2);
            uint32_t o = r*PITCH + 2*ltid;
            *(__nv_bfloat16*)(smb + OFF_W1 + o) = w1;
            *(__nv_bfloat16*)(smb + OFF_W2 + o) = w2;
        }
        const int cgrp = ltid >> 5, kk = ltid & 31;
        #pragma unroll
        for (int r = 0; r < 24; r++) {
            int n = 4*r + cgrp;
            __nv_bfloat16 b1, b2;
            bf16split(breg[r], b1, b2);
            uint32_t o = n*TP + 2*kk;
            *(__nv_bfloat16*)(smb + TC1 + o) = b1;
            *(__nv_bfloat16*)(smb + TC2 + o) = b2;
        }
    }
    __syncthreads();                               // ---- sync 3 ----

    // ---- MMA1 (warp 0): s = Asum @ wn1p^T -> sX ----
    if (w == 0) {
        float c[4][4];
        #pragma unroll
        for (int nt = 0; nt < 4; nt++)
            c[nt][0] = c[nt][1] = c[nt][2] = c[nt][3] = 0.f;
        const uint32_t a_off = (uint32_t)((l & 15)*PITCH + (l >> 4)*16);
        const uint32_t b_off = (uint32_t)((l & 7)*PITCH + ((l >> 3) & 1)*16);
        #pragma unroll
        for (int ks = 0; ks < 8; ks++) {
            uint32_t kb = ks*32;
            uint32_t a1[4], a2[4];
            ldsm4(a1, sb + OFF_TA1 + a_off + kb);
            ldsm4(a2, sb + OFF_TA2 + a_off + kb);
            #pragma unroll
            for (int nt = 0; nt < 4; nt++) {
                uint32_t b1[2], b2[2];
                uint32_t bo = b_off + (uint32_t)(nt*8*PITCH) + kb;
                ldsm2(b1, sb + OFF_W1 + bo);
                ldsm2(b2, sb + OFF_W2 + bo);
                mma_bf16(c[nt], a1, b1);
                mma_bf16(c[nt], a1, b2);
                mma_bf16(c[nt], a2, b1);
            }
        }
        const int nd = l >> 2, c0 = (l & 3)*2;
        #pragma unroll
        for (int nt = 0; nt < 4; nt++)
            *(float2*)&sf[SXO + nd*SXP + nt*8 + c0] = make_float2(c[nt][0], c[nt][1]);
    }
    __syncthreads();                               // ---- sync 4 ----

    // ---- x = relu(s/D + b) -> split into TX rows 0-7; zero rows 8-15 ----
    {
        const float invD = 1.0f / __ldg(D + node);
        float x = fmaxf(fmaf(sf[SXO + w*SXP + l], invD,
                             __ldg(bn1p+l) + __ldg(bn1s+l)), 0.f);
        __nv_bfloat16 xh, xl;
        bf16split(x, xh, xl);
        *(__nv_bfloat16*)(smb + TX1 + w*TP + 2*l) = xh;
        *(__nv_bfloat16*)(smb + TX2 + w*TP + 2*l) = xl;
        if (l < 20) {
            *(uint32_t*)(smb + TX1 + (8+w)*TP + 4*l) = 0u;
            *(uint32_t*)(smb + TX2 + (8+w)*TP + 4*l) = 0u;
        }
    }
    __syncthreads();                               // ---- sync 5 ----

    // ---- MMA2 (warps 0-2): {u1, v1, s2} = Xn1 @ {P,Q,wn2s}^T ----
    if (w < 3) {
        float c[4][4];
        #pragma unroll
        for (int nt = 0; nt < 4; nt++)
            c[nt][0] = c[nt][1] = c[nt][2] = c[nt][3] = 0.f;
        const uint32_t a_off = (uint32_t)((l & 15)*TP + (l >> 4)*16);
        const uint32_t b_off = (uint32_t)(w*32*TP + (l & 7)*TP + ((l >> 3) & 1)*16);
        #pragma unroll
        for (int ks = 0; ks < 2; ks++) {
            uint32_t kb = ks*32;
            uint32_t a1[4], a2[4];
            ldsm4(a1, sb + TX1 + a_off + kb);
            ldsm4(a2, sb + TX2 + a_off + kb);
            #pragma unroll
            for (int nt = 0; nt < 4; nt++) {
                uint32_t b1[2], b2[2];
                uint32_t bo = b_off + (uint32_t)(nt*8*TP) + kb;
                ldsm2(b1, sb + TC1 + bo);
                ldsm2(b2, sb + TC2 + bo);
                mma_bf16(c[nt], a1, b1);
                mma_bf16(c[nt], a1, b2);
                mma_bf16(c[nt], a2, b1);
            }
        }
        const int nd = l >> 2, c0 = (l & 3)*2;
        const int onode = blk*8 + nd;
        #pragma unroll
        for (int nt = 0; nt < 4; nt++) {
            const int h0 = nt*8 + c0;
            float2 r = make_float2(c[nt][0], c[nt][1]);
            if (w == 0) {
                r.x += __ldg(be1p+h0)   + __ldg(be1s+h0);
                r.y += __ldg(be1p+h0+1) + __ldg(be1s+h0+1);
                *(float2*)&g_u1[onode*HH + h0] = r;
            } else if (w == 1) {
                *(float2*)&g_v1[onode*HH + h0] = r;
            } else {
                r.x += __ldg(bn2p+h0)   + __ldg(bn2s+h0);
                r.y += __ldg(bn2p+h0+1) + __ldg(bn2s+h0+1);
                *(float2*)&g_s2[onode*HH + h0] = r;
            }
        }
    }
}

// ============================================================================
// K2' (lightweight): Asum1 -> Xn2 -> u2/v2. NO T2 write. (T1 read as fp16)
// ============================================================================
__global__ __launch_bounds__(256) void k2(const int* __restrict__ dst,
                                          const float* __restrict__ D,
                                          const float* __restrict__ wn2p,
                                          const float* __restrict__ we2p,
                                          const float* __restrict__ be2p,
                                          const float* __restrict__ be2s) {
    __shared__ float sWn[32*33];
    __shared__ float sP[32*33];
    __shared__ float sQ[32*33];
    const int tid = threadIdx.x, blk = blockIdx.x;
    const int w = tid >> 5, h = tid & 31;

    #pragma unroll
    for (int r = 0; r < 4; r++) {
        int idx = tid + 256*r;
        int hh = idx >> 5, h2 = idx & 31;
        sWn[h2*33 + hh] = __ldg(wn2p + idx);
        float wa = __ldg(we2p + hh*64 + h2);
        float wb = __ldg(we2p + hh*64 + 32 + h2);
        sP[h2*33 + hh] = 0.5f*(wa + wb);
        sQ[h2*33 + hh] = 0.5f*(wb - wa);
    }

    const int node = blk*8 + w;
    const float u1h = g_u1[node*HH + h];
    const int* de = dst + node*DEGQ;
    const size_t ebase = (size_t)node*DEGQ;
    float asum = 0.f;
    #pragma unroll
    for (int j = 0; j < DEGQ; j++) {
        int d = __ldg(de + j);
        float val = u1h + g_v1[d*HH + h] + __half2float(g_Th[(ebase + j)*HH + h]);
        asum += fmaxf(val, 0.f);
    }
    __syncthreads();

    const float invD = 1.0f / __ldg(D + node);
    float s = 0.f;
    #pragma unroll
    for (int h2 = 0; h2 < 32; h2++) {
        float aa = __shfl_sync(0xffffffffu, asum, h2);
        s = fmaf(aa, sWn[h2*33 + h], s);
    }
    float x = fmaxf(fmaf(s, invD, g_s2[node*HH + h]), 0.f);
    float u = __ldg(be2p+h) + __ldg(be2s+h), vv = 0.f;
    #pragma unroll
    for (int h2 = 0; h2 < 32; h2++) {
        float xx = __shfl_sync(0xffffffffu, x, h2);
        u  = fmaf(xx, sP[h2*33 + h], u);
        vv = fmaf(xx, sQ[h2*33 + h], vv);
    }
    g_u2[node*HH + h] = u;
    g_v2[node*HH + h] = vv;
}

// ============================================================================
// K3' (fused): vals1 recompute (fp16 T1) -> T2 MMA in regs -> classifier
// ============================================================================
#define K2P 80
__global__ __launch_bounds__(256) void k3(const int* __restrict__ dst,
                                          const float* __restrict__ we2s,
                                          const float* __restrict__ wc,
                                          const float* __restrict__ bc,
                                          float* __restrict__ out) {
    __shared__ __align__(16) unsigned char sA1[128*K2P];
    __shared__ __align__(16) unsigned char sA2[128*K2P];
    __shared__ __align__(16) unsigned char sB1[32*K2P];
    __shared__ __align__(16) unsigned char sB2[32*K2P];

    const int tid = threadIdx.x, blk = blockIdx.x;
    const int w = tid >> 5, l = tid & 31;

    #pragma unroll
    for (int r = 0; r < 4; r++) {
        int idx = tid + 256*r;
        int n = idx >> 5, k = idx & 31;
        __nv_bfloat16 b1, b2;
        bf16split(__ldg(we2s + idx), b1, b2);
        uint32_t o = n*K2P + 2*k;
        *(__nv_bfloat16*)(sB1 + o) = b1;
        *(__nv_bfloat16*)(sB2 + o) = b2;
    }

    const int node = blk*8 + w;
    const float u1h = g_u1[node*HH + l];
    const int* de = dst + node*DEGQ;
    const size_t ebase = (size_t)node*DEGQ;
    #pragma unroll
    for (int j = 0; j < DEGQ; j++) {
        int d = __ldg(de + j);
        float val = u1h + g_v1[d*HH + l] + __half2float(g_Th[(ebase + j)*HH + l]);
        val = fmaxf(val, 0.f);
        __nv_bfloat16 b1, b2;
        bf16split(val, b1, b2);
        uint32_t m1 = (uint32_t)__bfloat16_as_ushort(b1);
        uint32_t m2 = (uint32_t)__bfloat16_as_ushort(b2);
        uint32_t o1 = __shfl_down_sync(0xffffffffu, m1, 1);
        uint32_t o2 = __shfl_down_sync(0xffffffffu, m2, 1);
        if (!(l & 1)) {
            const int row = w*DEGQ + j;
            *(uint32_t*)(sA1 + row*K2P + l*2) = m1 | (o1 << 16);
            *(uint32_t*)(sA2 + row*K2P + l*2) = m2 | (o2 << 16);
        }
    }
    __syncthreads();

    float c[4][4];
    #pragma unroll
    for (int nt = 0; nt < 4; nt++)
        c[nt][0] = c[nt][1] = c[nt][2] = c[nt][3] = 0.f;
    {
        const uint32_t a1_base = smem_u32(sA1) + (uint32_t)((w*16 + (l & 15))*K2P + (l >> 4)*16);
        const uint32_t a2_base = smem_u32(sA2) + (uint32_t)((w*16 + (l & 15))*K2P + (l >> 4)*16);
        const uint32_t b1_base = smem_u32(sB1) + (uint32_t)(((l & 7))*K2P + ((l >> 3) & 1)*16);
        const uint32_t b2_base = smem_u32(sB2) + (uint32_t)(((l & 7))*K2P + ((l >> 3) & 1)*16);

        #pragma unroll
        for (int ks = 0; ks < 2; ks++) {
            const uint32_t kb = ks*32;
            uint32_t a1[4], a2[4];
            ldsm4(a1, a1_base + kb);
            ldsm4(a2, a2_base + kb);
            #pragma unroll
            for (int nt = 0; nt < 4; nt++) {
                uint32_t b1[2], b2[2];
                ldsm2(b1, b1_base + nt*8*K2P + kb);
                ldsm2(b2, b2_base + nt*8*K2P + kb);
                mma_bf16(c[nt], a1, b1);
                mma_bf16(c[nt], a1, b2);
                mma_bf16(c[nt], a2, b1);
            }
        }
    }

    const int lg = l & 3, r0 = l >> 2;
    const size_t e0 = (size_t)blk*128 + w*16 + r0;
    const size_t e1 = e0 + 8;
    const int d0 = __ldg(dst + e0);
    const int d1 = __ldg(dst + e1);
    float acc0 = 0.f, acc1 = 0.f;
    #pragma unroll
    for (int nt = 0; nt < 4; nt++) {
        const int h0 = nt*8 + lg*2;
        const float2 wcv = *(const float2*)&wc[h0];
        const float2 uu  = *(const float2*)&g_u2[node*HH + h0];
        const float2 va  = *(const float2*)&g_v2[d0*HH + h0];
        const float2 vb  = *(const float2*)&g_v2[d1*HH + h0];
        acc0 += fmaxf(uu.x + va.x + c[nt][0], 0.f) * wcv.x
              + fmaxf(uu.y + va.y + c[nt][1], 0.f) * wcv.y;
        acc1 += fmaxf(uu.x + vb.x + c[nt][2], 0.f) * wcv.x
              + fmaxf(uu.y + vb.y + c[nt][3], 0.f) * wcv.y;
    }
    acc0 += __shfl_xor_sync(0xffffffffu, acc0, 1);
    acc0 += __shfl_xor_sync(0xffffffffu, acc0, 2);
    acc1 += __shfl_xor_sync(0xffffffffu, acc1, 1);
    acc1 += __shfl_xor_sync(0xffffffffu, acc1, 2);
    if (lg == 0) {
        const float bcv = __ldg(bc);
        out[e0] = 1.f / (1.f + __expf(-(acc0 + bcv)));
        out[e1] = 1.f / (1.f + __expf(-(acc1 + bcv)));
    }
}

// ============================================================================
extern "C" void kernel_launch(void* const* d_in, const int* in_sizes, int n_in,
                              void* d_out, int out_size) {
    const float* X    = (const float*)d_in[0];
    const int*   dst  = (const int*)  d_in[2];
    const float* D    = (const float*)d_in[3];
    const float* wn1p = (const float*)d_in[4];
    const float* bn1p = (const float*)d_in[5];
    const float* bn1s = (const float*)d_in[7];
    const float* we1p = (const float*)d_in[8];
    const float* be1p = (const float*)d_in[9];
    const float* we1s = (const float*)d_in[10];
    const float* be1s = (const float*)d_in[11];
    const float* wn2p = (const float*)d_in[12];
    const float* bn2p = (const float*)d_in[13];
    const float* wn2s = (const float*)d_in[14];
    const float* bn2s = (const float*)d_in[15];
    const float* we2p = (const float*)d_in[16];
    const float* be2p = (const float*)d_in[17];
    const float* we2s = (const float*)d_in[18];
    const float* be2s = (const float*)d_in[19];
    const float* wc   = (const float*)d_in[20];
    const float* bc   = (const float*)d_in[21];
    float* out = (float*)d_out;

    cudaFuncSetAttribute(k1, cudaFuncAttributeMaxDynamicSharedMemorySize, K1_SMEM);

    k1 <<<NN/8, 256, K1_SMEM>>>(X, dst, D, we1s, wn1p, bn1p, bn1s,
                                we1p, be1p, be1s, wn2s, bn2p, bn2s);
    k2 <<<NN/8, 256>>>(dst, D, wn2p, we2p, be2p, be2s);
    k3 <<<NN/8, 256>>>(dst, we2s, wc, bc, out);
}

// round 14
// speedup vs baseline: 1.4921x; 1.1546x over previous
#include <cuda_runtime.h>
#include <cuda_bf16.h>
#include <cuda_fp16.h>
#include <cstdint>

#define NN   50000
#define DEGQ 16
#define EE   (NN*DEGQ)
#define HH   32
#define FIN  128
#define NPB  40      // nodes per k1 block
#define TPB  5       // edge tiles per k1 block (8 nodes / 128 edges each)

// ---------------- scratch (device globals; no allocation) ----------------
__device__ __half g_Th[(size_t)EE*HH];     // T1 in fp16 : 51.2MB
__device__ float g_u1[NN*HH];
__device__ float g_v1[NN*HH];
__device__ float g_s2[NN*HH];
__device__ float g_u2[NN*HH];
__device__ float g_v2[NN*HH];

// ---------------- mma.sync helpers ----------------
__device__ __forceinline__ uint32_t smem_u32(const void* p) {
    uint32_t a;
    asm("{ .reg .u64 t; cvta.to.shared.u64 t, %1; cvt.u32.u64 %0, t; }" : "=r"(a) : "l"(p));
    return a;
}
__device__ __forceinline__ void ldsm4(uint32_t* r, uint32_t addr) {
    asm volatile("ldmatrix.sync.aligned.m8n8.x4.shared.b16 {%0,%1,%2,%3}, [%4];"
        : "=r"(r[0]), "=r"(r[1]), "=r"(r[2]), "=r"(r[3]) : "r"(addr));
}
__device__ __forceinline__ void ldsm2(uint32_t* r, uint32_t addr) {
    asm volatile("ldmatrix.sync.aligned.m8n8.x2.shared.b16 {%0,%1}, [%2];"
        : "=r"(r[0]), "=r"(r[1]) : "r"(addr));
}
__device__ __forceinline__ void mma_bf16(float* c, const uint32_t* a, const uint32_t* b) {
    asm volatile("mma.sync.aligned.m16n8k16.row.col.f32.bf16.bf16.f32 "
        "{%0,%1,%2,%3}, {%4,%5,%6,%7}, {%8,%9}, {%0,%1,%2,%3};"
        : "+f"(c[0]), "+f"(c[1]), "+f"(c[2]), "+f"(c[3])
        : "r"(a[0]), "r"(a[1]), "r"(a[2]), "r"(a[3]), "r"(b[0]), "r"(b[1]));
}
__device__ __forceinline__ void bf16split(float v, __nv_bfloat16& hi, __nv_bfloat16& lo) {
    hi = __float2bfloat16(v);
    lo = __float2bfloat16(v - __bfloat162float(hi));
}
__device__ __forceinline__ uint32_t cvt2bf(float lo, float hi) {
    uint32_t r;
    asm("cvt.rn.bf16x2.f32 %0, %1, %2;" : "=r"(r) : "f"(hi), "f"(lo));
    return r;
}

// ---- k1 smem layout (bytes). Main pitch 272; tail pitch 80. ----
#define PITCH    272
#define OFF_A1   0
#define OFF_A2   34816
#define OFF_W1   69632                  // we1s (main), then wn1p (tail, restaged)
#define OFF_W2   78336
#define OFF_TA1  87040                  // asum split hi : 40 x 272
#define OFF_TA2  97920                  // asum split lo
#define K1_SMEM  108800                 // 2 CTAs/SM (217.6KB of 228KB)
// tail aliases inside the A region (free after the tile loop):
#define TC1  0                          // B'' = [P;Q;wn2s] hi : 96 x 80
#define TC2  7680
#define TX1  15360                      // x split hi : 48 x 80 (rows 40-47 zero)
#define TX2  19200
#define SXO  (23040/4)                  // sX floats : 40 x 34
#define SXP  34
#define TP   80

// ---- one MMA2 task: rows [rt*16, rt*16+16) of x  @  B'' section sec ----
__device__ __forceinline__ void mma2_task(int task, uint32_t sb, int blk, int l,
        const float* __restrict__ be1p, const float* __restrict__ be1s,
        const float* __restrict__ bn2p, const float* __restrict__ bn2s) {
    const int rt = task / 3, sec = task - rt*3;
    float c[4][4];
    #pragma unroll
    for (int nt = 0; nt < 4; nt++)
        c[nt][0] = c[nt][1] = c[nt][2] = c[nt][3] = 0.f;
    const uint32_t a_off = (uint32_t)((rt*16 + (l & 15))*TP + (l >> 4)*16);
    const uint32_t b_off = (uint32_t)((sec*32 + (l & 7))*TP + ((l >> 3) & 1)*16);
    #pragma unroll
    for (int ks = 0; ks < 2; ks++) {
        const uint32_t kb = ks*32;
        uint32_t a1[4], a2[4];
        ldsm4(a1, sb + TX1 + a_off + kb);
        ldsm4(a2, sb + TX2 + a_off + kb);
        #pragma unroll
        for (int nt = 0; nt < 4; nt++) {
            uint32_t b1[2], b2[2];
            const uint32_t bo = b_off + (uint32_t)(nt*8*TP) + kb;
            ldsm2(b1, sb + TC1 + bo);
            ldsm2(b2, sb + TC2 + bo);
            mma_bf16(c[nt], a1, b1);
            mma_bf16(c[nt], a1, b2);
            mma_bf16(c[nt], a2, b1);
        }
    }
    const int r0 = l >> 2, c0 = (l & 3)*2;
    #pragma unroll
    for (int nt = 0; nt < 4; nt++) {
        const int h0 = nt*8 + c0;
        #pragma unroll
        for (int half = 0; half < 2; half++) {
            const int row = rt*16 + r0 + half*8;
            if (row < NPB) {
                const int node = blk*NPB + row;
                float2 r = make_float2(c[nt][half*2], c[nt][half*2+1]);
                if (sec == 0) {
                    r.x += __ldg(be1p+h0)   + __ldg(be1s+h0);
                    r.y += __ldg(be1p+h0+1) + __ldg(be1s+h0+1);
                    *(float2*)&g_u1[node*HH + h0] = r;
                } else if (sec == 1) {
                    *(float2*)&g_v1[node*HH + h0] = r;
                } else {
                    r.x += __ldg(bn2p+h0)   + __ldg(bn2s+h0);
                    r.y += __ldg(bn2p+h0+1) + __ldg(bn2s+h0+1);
                    *(float2*)&g_s2[node*HH + h0] = r;
                }
            }
        }
    }
}

// ============================================================================
// K1: per block 40 nodes / 640 edges (5 tiles of 128 edges).
//   Weight conversion once; 5x [gather -> main MMA -> fp16 T1].
//   Tail once for 40 nodes: MMA1 (s), x, MMA2 (u1/v1/s2).
// ============================================================================
__global__ __launch_bounds__(256, 2) void k1(const float* __restrict__ X,
                                             const int*   __restrict__ dst,
                                             const float* __restrict__ D,
                                             const float* __restrict__ we1s,
                                             const float* __restrict__ wn1p,
                                             const float* __restrict__ bn1p,
                                             const float* __restrict__ bn1s,
                                             const float* __restrict__ we1p,
                                             const float* __restrict__ be1p,
                                             const float* __restrict__ be1s,
                                             const float* __restrict__ wn2s,
                                             const float* __restrict__ bn2p,
                                             const float* __restrict__ bn2s) {
    extern __shared__ unsigned char smb[];
    float* sf = (float*)smb;
    const uint32_t sb = smem_u32(smb);

    const int tid = threadIdx.x;
    const int blk = blockIdx.x;
    const int w = tid >> 5, l = tid & 31;

    // ---- phase A (once): we1s (32 x 128 fp32) -> W1,W2 bf16 ----
    #pragma unroll
    for (int r = 0; r < 16; r++) {
        int idx = tid + 256*r;
        int h = idx >> 7, k = idx & 127;
        __nv_bfloat16 w1, w2;
        bf16split(__ldg(we1s + idx), w1, w2);
        uint32_t o = h*PITCH + 2*k;
        *(__nv_bfloat16*)(smb + OFF_W1 + o) = w1;
        *(__nv_bfloat16*)(smb + OFF_W2 + o) = w2;
    }

    // prefetch registers for warps 4-7 (live across the tile loop)
    float wreg[32];
    float breg[24];

    #pragma unroll 1
    for (int t = 0; t < TPB; t++) {
        // ---- gather tile t: warp w -> node blk*40 + t*8 + w ----
        const int node = blk*NPB + t*8 + w;
        const float4 xv = ((const float4*)(X + (size_t)node*FIN))[l];
        float4 asum = make_float4(0.f, 0.f, 0.f, 0.f);
        const int* de = dst + node*DEGQ;
        #pragma unroll
        for (int j = 0; j < DEGQ; j++) {
            int d = __ldg(de + j);
            float4 g = ((const float4*)(X + (size_t)d*FIN))[l];
            float4 a;
            a.x = fabsf(xv.x - g.x);
            a.y = fabsf(xv.y - g.y);
            a.z = fabsf(xv.z - g.z);
            a.w = fabsf(xv.w - g.w);
            asum.x += a.x; asum.y += a.y; asum.z += a.z; asum.w += a.w;

            uint32_t p01 = cvt2bf(a.x, a.y);
            uint32_t p23 = cvt2bf(a.z, a.w);
            float hx = __uint_as_float(p01 << 16);
            float hy = __uint_as_float(p01 & 0xFFFF0000u);
            float hz = __uint_as_float(p23 << 16);
            float hw = __uint_as_float(p23 & 0xFFFF0000u);
            uint32_t q01 = cvt2bf(a.x - hx, a.y - hy);
            uint32_t q23 = cvt2bf(a.z - hz, a.w - hw);
            uint64_t hiw = (uint64_t)p01 | ((uint64_t)p23 << 32);
            uint64_t low = (uint64_t)q01 | ((uint64_t)q23 << 32);

            const int row = w*DEGQ + j;
            uint32_t o = row*PITCH + l*8;
            *(uint64_t*)(smb + OFF_A1 + o) = hiw;
            *(uint64_t*)(smb + OFF_A2 + o) = low;
        }
        // asum -> TA row t*8+w (bf16 split)
        {
            uint32_t p01 = cvt2bf(asum.x, asum.y);
            uint32_t p23 = cvt2bf(asum.z, asum.w);
            float hx = __uint_as_float(p01 << 16);
            float hy = __uint_as_float(p01 & 0xFFFF0000u);
            float hz = __uint_as_float(p23 << 16);
            float hw = __uint_as_float(p23 & 0xFFFF0000u);
            uint32_t q01 = cvt2bf(asum.x - hx, asum.y - hy);
            uint32_t q23 = cvt2bf(asum.z - hz, asum.w - hw);
            uint64_t hiw = (uint64_t)p01 | ((uint64_t)p23 << 32);
            uint64_t low = (uint64_t)q01 | ((uint64_t)q23 << 32);
            const int tr = t*8 + w;
            *(uint64_t*)(smb + OFF_TA1 + tr*PITCH + l*8) = hiw;
            *(uint64_t*)(smb + OFF_TA2 + tr*PITCH + l*8) = low;
        }
        __syncthreads();

        if (w < 4) {
            // ---- main MMA: warp w -> tile rows 32w..32w+31, all 32 cols ----
            const int wr = w*32;
            float c[2][4][4];
            #pragma unroll
            for (int tt = 0; tt < 2; tt++)
                #pragma unroll
                for (int nt = 0; nt < 4; nt++)
                    c[tt][nt][0] = c[tt][nt][1] = c[tt][nt][2] = c[tt][nt][3] = 0.f;

            const uint32_t a_off = (uint32_t)((wr + (l & 15))*PITCH + (l >> 4)*16);
            const uint32_t b_off = (uint32_t)(((l & 7))*PITCH + ((l >> 3) & 1)*16);

            #pragma unroll
            for (int ks = 0; ks < 8; ks++) {
                const uint32_t kb = ks*32;
                uint32_t bfr[4][2][2];
                #pragma unroll
                for (int nt = 0; nt < 4; nt++) {
                    const uint32_t bo = b_off + (uint32_t)(nt*8*PITCH) + kb;
                    ldsm2(bfr[nt][0], sb + OFF_W1 + bo);
                    ldsm2(bfr[nt][1], sb + OFF_W2 + bo);
                }
                #pragma unroll
                for (int tt = 0; tt < 2; tt++) {
                    uint32_t a1[4], a2[4];
                    ldsm4(a1, sb + OFF_A1 + a_off + (uint32_t)(tt*16*PITCH) + kb);
                    ldsm4(a2, sb + OFF_A2 + a_off + (uint32_t)(tt*16*PITCH) + kb);
                    #pragma unroll
                    for (int nt = 0; nt < 4; nt++) {
                        mma_bf16(c[tt][nt], a1, bfr[nt][0]);
                        mma_bf16(c[tt][nt], a1, bfr[nt][1]);
                        mma_bf16(c[tt][nt], a2, bfr[nt][0]);
                    }
                }
            }

            // epilogue: fp16 T1
            const int r0 = l >> 2, c0 = (l & 3)*2;
            #pragma unroll
            for (int tt = 0; tt < 2; tt++) {
                const size_t base = (size_t)blk*(NPB*DEGQ) + t*128 + wr + tt*16;
                #pragma unroll
                for (int nt = 0; nt < 4; nt++) {
                    __half2 h01 = __floats2half2_rn(c[tt][nt][0], c[tt][nt][1]);
                    __half2 h23 = __floats2half2_rn(c[tt][nt][2], c[tt][nt][3]);
                    *(__half2*)&g_Th[(base + r0)*HH + nt*8 + c0]     = h01;
                    *(__half2*)&g_Th[(base + r0 + 8)*HH + nt*8 + c0] = h23;
                }
            }
        } else if (t == 0) {
            // ---- prefetch tail weights into registers (hidden under MMA) ----
            const int ltid = tid - 128;
            #pragma unroll
            for (int r = 0; r < 32; r++)
                wreg[r] = __ldg(wn1p + ltid + 128*r);
            const int cgrp = ltid >> 5, kk = ltid & 31;
            #pragma unroll
            for (int r = 0; r < 8; r++) {
                int n = 4*r + cgrp;
                float wa = __ldg(we1p + n*64 + kk), wb = __ldg(we1p + n*64 + 32 + kk);
                breg[r] = 0.5f*(wa + wb);
            }
            #pragma unroll
            for (int r = 8; r < 16; r++) {
                int h = 4*(r-8) + cgrp;
                float wa = __ldg(we1p + h*64 + kk), wb = __ldg(we1p + h*64 + 32 + kk);
                breg[r] = 0.5f*(wb - wa);
            }
            #pragma unroll
            for (int r = 16; r < 24; r++) {
                int h = 4*(r-16) + cgrp;
                breg[r] = __ldg(wn2s + h*32 + kk);
            }
        }
        __syncthreads();
    }

    // ---- tail staging: warps 4-7 STS weights; warps 0-3 zero TX pad rows ----
    if (w >= 4) {
        const int ltid = tid - 128;
        #pragma unroll
        for (int r = 0; r < 32; r++) {
            __nv_bfloat16 w1, w2;
            bf16split(wreg[r], w1, w2);
            uint32_t o = r*PITCH + 2*ltid;
            *(__nv_bfloat16*)(smb + OFF_W1 + o) = w1;
            *(__nv_bfloat16*)(smb + OFF_W2 + o) = w2;
        }
        const int cgrp = ltid >> 5, kk = ltid & 31;
        #pragma unroll
        for (int r = 0; r < 24; r++) {
            int n = 4*r + cgrp;
            __nv_bfloat16 b1, b2;
            bf16split(breg[r], b1, b2);
            uint32_t o = n*TP + 2*kk;
            *(__nv_bfloat16*)(smb + TC1 + o) = b1;
            *(__nv_bfloat16*)(smb + TC2 + o) = b2;
        }
    } else {
        // zero x rows 40-47 (pad for MMA2 row-tile 2): 160 words per buffer
        #pragma unroll
        for (int r = 0; r < 2; r++) {
            int idx2 = tid + 128*r;
            if (idx2 < 160) {
                *(uint32_t*)(smb + TX1 + NPB*TP + idx2*4) = 0u;
                *(uint32_t*)(smb + TX2 + NPB*TP + idx2*4) = 0u;
            }
        }
    }
    __syncthreads();

    // ---- MMA1 (warps 0-2): s = Asum(40x128) @ wn1p^T -> sX ----
    // warp row-tiles: 0-15, 16-31, 24-39 (overlap; warp 2 writes rows 32-39 only)
    if (w < 3) {
        const int rowbase = (w == 2) ? 24 : w*16;
        float c[4][4];
        #pragma unroll
        for (int nt = 0; nt < 4; nt++)
            c[nt][0] = c[nt][1] = c[nt][2] = c[nt][3] = 0.f;
        const uint32_t a_off = (uint32_t)((rowbase + (l & 15))*PITCH + (l >> 4)*16);
        const uint32_t b_off = (uint32_t)((l & 7)*PITCH + ((l >> 3) & 1)*16);
        #pragma unroll
        for (int ks = 0; ks < 8; ks++) {
            const uint32_t kb = ks*32;
            uint32_t a1[4], a2[4];
            ldsm4(a1, sb + OFF_TA1 + a_off + kb);
            ldsm4(a2, sb + OFF_TA2 + a_off + kb);
            #pragma unroll
            for (int nt = 0; nt < 4; nt++) {
                uint32_t b1[2], b2[2];
                const uint32_t bo = b_off + (uint32_t)(nt*8*PITCH) + kb;
                ldsm2(b1, sb + OFF_W1 + bo);
                ldsm2(b2, sb + OFF_W2 + bo);
                mma_bf16(c[nt], a1, b1);
                mma_bf16(c[nt], a1, b2);
                mma_bf16(c[nt], a2, b1);
            }
        }
        const int r0 = l >> 2, c0 = (l & 3)*2;
        #pragma unroll
        for (int nt = 0; nt < 4; nt++) {
            const int nd0 = rowbase + r0;
            if (w != 2)
                *(float2*)&sf[SXO + nd0*SXP + nt*8 + c0] = make_float2(c[nt][0], c[nt][1]);
            *(float2*)&sf[SXO + (nd0+8)*SXP + nt*8 + c0] = make_float2(c[nt][2], c[nt][3]);
        }
    }
    __syncthreads();

    // ---- x = relu(s/D + b) for 40 nodes x 32 h -> TX (split) ----
    #pragma unroll
    for (int r = 0; r < 5; r++) {
        int idx = tid + 256*r;                 // 0..1279
        int nd = idx >> 5, h = idx & 31;
        int node = blk*NPB + nd;
        const float invD = 1.0f / __ldg(D + node);
        float x = fmaxf(fmaf(sf[SXO + nd*SXP + h], invD,
                             __ldg(bn1p+h) + __ldg(bn1s+h)), 0.f);
        __nv_bfloat16 xh, xl;
        bf16split(x, xh, xl);
        *(__nv_bfloat16*)(smb + TX1 + nd*TP + 2*h) = xh;
        *(__nv_bfloat16*)(smb + TX2 + nd*TP + 2*h) = xl;
    }
    __syncthreads();

    // ---- MMA2: 9 tasks (3 row-tiles x {P,Q,wn2s}); warp w -> task w, warp 7 also task 8
    mma2_task(w, sb, blk, l, be1p, be1s, bn2p, bn2s);
    if (w == 7)
        mma2_task(8, sb, blk, l, be1p, be1s, bn2p, bn2s);
}

// ============================================================================
// K2' (lightweight): Asum1 -> Xn2 -> u2/v2. NO T2 write. (T1 read as fp16)
// ============================================================================
__global__ __launch_bounds__(256) void k2(const int* __restrict__ dst,
                                          const float* __restrict__ D,
                                          const float* __restrict__ wn2p,
                                          const float* __restrict__ we2p,
                                          const float* __restrict__ be2p,
                                          const float* __restrict__ be2s) {
    __shared__ float sWn[32*33];
    __shared__ float sP[32*33];
    __shared__ float sQ[32*33];
    const int tid = threadIdx.x, blk = blockIdx.x;
    const int w = tid >> 5, h = tid & 31;

    #pragma unroll
    for (int r = 0; r < 4; r++) {
        int idx = tid + 256*r;
        int hh = idx >> 5, h2 = idx & 31;
        sWn[h2*33 + hh] = __ldg(wn2p + idx);
        float wa = __ldg(we2p + hh*64 + h2);
        float wb = __ldg(we2p + hh*64 + 32 + h2);
        sP[h2*33 + hh] = 0.5f*(wa + wb);
        sQ[h2*33 + hh] = 0.5f*(wb - wa);
    }

    const int node = blk*8 + w;
    const float u1h = g_u1[node*HH + h];
    const int* de = dst + node*DEGQ;
    const size_t ebase = (size_t)node*DEGQ;
    float asum = 0.f;
    #pragma unroll
    for (int j = 0; j < DEGQ; j++) {
        int d = __ldg(de + j);
        float val = u1h + g_v1[d*HH + h] + __half2float(g_Th[(ebase + j)*HH + h]);
        asum += fmaxf(val, 0.f);
    }
    __syncthreads();

    const float invD = 1.0f / __ldg(D + node);
    float s = 0.f;
    #pragma unroll
    for (int h2 = 0; h2 < 32; h2++) {
        float aa = __shfl_sync(0xffffffffu, asum, h2);
        s = fmaf(aa, sWn[h2*33 + h], s);
    }
    float x = fmaxf(fmaf(s, invD, g_s2[node*HH + h]), 0.f);
    float u = __ldg(be2p+h) + __ldg(be2s+h), vv = 0.f;
    #pragma unroll
    for (int h2 = 0; h2 < 32; h2++) {
        float xx = __shfl_sync(0xffffffffu, x, h2);
        u  = fmaf(xx, sP[h2*33 + h], u);
        vv = fmaf(xx, sQ[h2*33 + h], vv);
    }
    g_u2[node*HH + h] = u;
    g_v2[node*HH + h] = vv;
}

// ============================================================================
// K3' (fused): vals1 recompute (fp16 T1) -> T2 MMA in regs -> classifier
// ============================================================================
#define K2P 80
__global__ __launch_bounds__(256) void k3(const int* __restrict__ dst,
                                          const float* __restrict__ we2s,
                                          const float* __restrict__ wc,
                                          const float* __restrict__ bc,
                                          float* __restrict__ out) {
    __shared__ __align__(16) unsigned char sA1[128*K2P];
    __shared__ __align__(16) unsigned char sA2[128*K2P];
    __shared__ __align__(16) unsigned char sB1[32*K2P];
    __shared__ __align__(16) unsigned char sB2[32*K2P];

    const int tid = threadIdx.x, blk = blockIdx.x;
    const int w = tid >> 5, l = tid & 31;

    #pragma unroll
    for (int r = 0; r < 4; r++) {
        int idx = tid + 256*r;
        int n = idx >> 5, k = idx & 31;
        __nv_bfloat16 b1, b2;
        bf16split(__ldg(we2s + idx), b1, b2);
        uint32_t o = n*K2P + 2*k;
        *(__nv_bfloat16*)(sB1 + o) = b1;
        *(__nv_bfloat16*)(sB2 + o) = b2;
    }

    const int node = blk*8 + w;
    const float u1h = g_u1[node*HH + l];
    const int* de = dst + node*DEGQ;
    const size_t ebase = (size_t)node*DEGQ;
    #pragma unroll
    for (int j = 0; j < DEGQ; j++) {
        int d = __ldg(de + j);
        float val = u1h + g_v1[d*HH + l] + __half2float(g_Th[(ebase + j)*HH + l]);
        val = fmaxf(val, 0.f);
        __nv_bfloat16 b1, b2;
        bf16split(val, b1, b2);
        uint32_t m1 = (uint32_t)__bfloat16_as_ushort(b1);
        uint32_t m2 = (uint32_t)__bfloat16_as_ushort(b2);
        uint32_t o1 = __shfl_down_sync(0xffffffffu, m1, 1);
        uint32_t o2 = __shfl_down_sync(0xffffffffu, m2, 1);
        if (!(l & 1)) {
            const int row = w*DEGQ + j;
            *(uint32_t*)(sA1 + row*K2P + l*2) = m1 | (o1 << 16);
            *(uint32_t*)(sA2 + row*K2P + l*2) = m2 | (o2 << 16);
        }
    }
    __syncthreads();

    float c[4][4];
    #pragma unroll
    for (int nt = 0; nt < 4; nt++)
        c[nt][0] = c[nt][1] = c[nt][2] = c[nt][3] = 0.f;
    {
        const uint32_t a1_base = smem_u32(sA1) + (uint32_t)((w*16 + (l & 15))*K2P + (l >> 4)*16);
        const uint32_t a2_base = smem_u32(sA2) + (uint32_t)((w*16 + (l & 15))*K2P + (l >> 4)*16);
        const uint32_t b1_base = smem_u32(sB1) + (uint32_t)(((l & 7))*K2P + ((l >> 3) & 1)*16);
        const uint32_t b2_base = smem_u32(sB2) + (uint32_t)(((l & 7))*K2P + ((l >> 3) & 1)*16);

        #pragma unroll
        for (int ks = 0; ks < 2; ks++) {
            const uint32_t kb = ks*32;
            uint32_t a1[4], a2[4];
            ldsm4(a1, a1_base + kb);
            ldsm4(a2, a2_base + kb);
            #pragma unroll
            for (int nt = 0; nt < 4; nt++) {
                uint32_t b1[2], b2[2];
                ldsm2(b1, b1_base + nt*8*K2P + kb);
                ldsm2(b2, b2_base + nt*8*K2P + kb);
                mma_bf16(c[nt], a1, b1);
                mma_bf16(c[nt], a1, b2);
                mma_bf16(c[nt], a2, b1);
            }
        }
    }

    const int lg = l & 3, r0 = l >> 2;
    const size_t e0 = (size_t)blk*128 + w*16 + r0;
    const size_t e1 = e0 + 8;
    const int d0 = __ldg(dst + e0);
    const int d1 = __ldg(dst + e1);
    float acc0 = 0.f, acc1 = 0.f;
    #pragma unroll
    for (int nt = 0; nt < 4; nt++) {
        const int h0 = nt*8 + lg*2;
        const float2 wcv = *(const float2*)&wc[h0];
        const float2 uu  = *(const float2*)&g_u2[node*HH + h0];
        const float2 va  = *(const float2*)&g_v2[d0*HH + h0];
        const float2 vb  = *(const float2*)&g_v2[d1*HH + h0];
        acc0 += fmaxf(uu.x + va.x + c[nt][0], 0.f) * wcv.x
              + fmaxf(uu.y + va.y + c[nt][1], 0.f) * wcv.y;
        acc1 += fmaxf(uu.x + vb.x + c[nt][2], 0.f) * wcv.x
              + fmaxf(uu.y + vb.y + c[nt][3], 0.f) * wcv.y;
    }
    acc0 += __shfl_xor_sync(0xffffffffu, acc0, 1);
    acc0 += __shfl_xor_sync(0xffffffffu, acc0, 2);
    acc1 += __shfl_xor_sync(0xffffffffu, acc1, 1);
    acc1 += __shfl_xor_sync(0xffffffffu, acc1, 2);
    if (lg == 0) {
        const float bcv = __ldg(bc);
        out[e0] = 1.f / (1.f + __expf(-(acc0 + bcv)));
        out[e1] = 1.f / (1.f + __expf(-(acc1 + bcv)));
    }
}

// ============================================================================
extern "C" void kernel_launch(void* const* d_in, const int* in_sizes, int n_in,
                              void* d_out, int out_size) {
    const float* X    = (const float*)d_in[0];
    const int*   dst  = (const int*)  d_in[2];
    const float* D    = (const float*)d_in[3];
    const float* wn1p = (const float*)d_in[4];
    const float* bn1p = (const float*)d_in[5];
    const float* bn1s = (const float*)d_in[7];
    const float* we1p = (const float*)d_in[8];
    const float* be1p = (const float*)d_in[9];
    const float* we1s = (const float*)d_in[10];
    const float* be1s = (const float*)d_in[11];
    const float* wn2p = (const float*)d_in[12];
    const float* bn2p = (const float*)d_in[13];
    const float* wn2s = (const float*)d_in[14];
    const float* bn2s = (const float*)d_in[15];
    const float* we2p = (const float*)d_in[16];
    const float* be2p = (const float*)d_in[17];
    const float* we2s = (const float*)d_in[18];
    const float* be2s = (const float*)d_in[19];
    const float* wc   = (const float*)d_in[20];
    const float* bc   = (const float*)d_in[21];
    float* out = (float*)d_out;

    cudaFuncSetAttribute(k1, cudaFuncAttributeMaxDynamicSharedMemorySize, K1_SMEM);

    k1 <<<NN/NPB, 256, K1_SMEM>>>(X, dst, D, we1s, wn1p, bn1p, bn1s,
                                  we1p, be1p, be1s, wn2s, bn2p, bn2s);
    k2 <<<NN/8, 256>>>(dst, D, wn2p, we2p, be2p, be2s);
    k3 <<<NN/8, 256>>>(dst, we2s, wc, bc, out);
}